// round 1
// baseline (speedup 1.0000x reference)
#include <cuda_runtime.h>
#include <cuda_bf16.h>
#include <math.h>

// Problem shape (fixed by the dataset)
#define BB 4
#define TT 2048
#define DD 1024
#define NROWS (BB * TT)   // 8192

// ---------------------------------------------------------------------------
// Scratch (device globals — no allocation allowed anywhere)
// ---------------------------------------------------------------------------
__device__ float g_Q[(size_t)NROWS * DD];            // 32 MB
__device__ float g_K[(size_t)NROWS * DD];            // 32 MB
__device__ float g_V[(size_t)NROWS * DD];            // 32 MB
__device__ float g_O[(size_t)NROWS * DD];            // 32 MB
__device__ float g_S[(size_t)BB * TT * TT];          // 64 MB (scores / probs)

// ---------------------------------------------------------------------------
// Generic NN GEMM:  C[M,N] = A[M,K] @ B[K,N] (+bias), row-major everywhere.
// 64x64 tile, BK=16, 256 threads, 4x4 micro-tile per thread.
// CAUSAL_K: truncate K-loop at (blockIdx.y+1)*64 (for P@V with causal P).
// blockIdx.z batches with the given strides.
// ---------------------------------------------------------------------------
template <bool CAUSAL_K, bool HAS_BIAS>
__global__ void __launch_bounds__(256) gemm_nn(
    const float* __restrict__ A, const float* __restrict__ Bm,
    const float* __restrict__ bias, float* __restrict__ C,
    int K, int lda, int ldb, int ldc,
    size_t strideA, size_t strideB, size_t strideC)
{
    __shared__ float As[16][65];   // [k][m], padded: conflict-free transposed store
    __shared__ float Bs[16][64];   // [k][n]

    const int tid = threadIdx.x;
    const int tx = tid & 15;       // 0..15
    const int ty = tid >> 4;       // 0..15

    const int rowBlk = blockIdx.y * 64;
    const int colBlk = blockIdx.x * 64;

    const float* Ab = A + (size_t)blockIdx.z * strideA;
    const float* Bb_ = Bm + (size_t)blockIdx.z * strideB;
    float*       Cb = C + (size_t)blockIdx.z * strideC;

    int kEnd = K;
    if (CAUSAL_K) {
        int ke = (blockIdx.y + 1) * 64;
        kEnd = ke < K ? ke : K;
    }

    const float* Aptr = Ab + (size_t)rowBlk * lda;
    const float* Bptr = Bb_ + colBlk;

    const int am = tid >> 2;          // 0..63  (row within A tile)
    const int ak = (tid & 3) * 4;     // 0,4,8,12
    const int bk = tid >> 4;          // 0..15  (row within B tile)
    const int bn = (tid & 15) * 4;    // 0..60

    float acc[4][4] = {};

    for (int k0 = 0; k0 < kEnd; k0 += 16) {
        float4 av = *(const float4*)(Aptr + (size_t)am * lda + (k0 + ak));
        As[ak + 0][am] = av.x;
        As[ak + 1][am] = av.y;
        As[ak + 2][am] = av.z;
        As[ak + 3][am] = av.w;

        float4 bv = *(const float4*)(Bptr + (size_t)(k0 + bk) * ldb + bn);
        *(float4*)&Bs[bk][bn] = bv;

        __syncthreads();

        #pragma unroll
        for (int k = 0; k < 16; k++) {
            float af[4], bf[4];
            #pragma unroll
            for (int i = 0; i < 4; i++) af[i] = As[k][ty + 16 * i];
            #pragma unroll
            for (int j = 0; j < 4; j++) bf[j] = Bs[k][tx + 16 * j];
            #pragma unroll
            for (int i = 0; i < 4; i++)
                #pragma unroll
                for (int j = 0; j < 4; j++)
                    acc[i][j] += af[i] * bf[j];
        }
        __syncthreads();
    }

    #pragma unroll
    for (int j = 0; j < 4; j++) {
        const int n = colBlk + tx + 16 * j;
        const float bvv = HAS_BIAS ? bias[n] : 0.0f;
        #pragma unroll
        for (int i = 0; i < 4; i++) {
            const int m = rowBlk + ty + 16 * i;
            Cb[(size_t)m * ldc + n] = acc[i][j] + bvv;
        }
    }
}

// ---------------------------------------------------------------------------
// NT GEMM for scores:  S[t,s] = scale * sum_d Q[t,d] * K[s,d]
// Upper-triangle (fully masked) blocks skipped; diagonal-block garbage above
// the diagonal is never read (softmax reads s<=t) and gets zeroed by softmax.
// blockIdx.z = batch.
// ---------------------------------------------------------------------------
__global__ void __launch_bounds__(256) gemm_nt_causal(
    const float* __restrict__ Q, const float* __restrict__ Kmat,
    float* __restrict__ S, float scale)
{
    const int sBlk = blockIdx.x * 64;
    const int tBlk = blockIdx.y * 64;
    if (sBlk > tBlk + 63) return;   // entire block above the diagonal

    __shared__ float As[16][65];    // Q: [k][t]
    __shared__ float Bs[16][65];    // K: [k][s]

    const int tid = threadIdx.x;
    const int tx = tid & 15;
    const int ty = tid >> 4;

    const float* Qb = Q    + (size_t)blockIdx.z * TT * DD;
    const float* Kb = Kmat + (size_t)blockIdx.z * TT * DD;
    float*       Sb = S    + (size_t)blockIdx.z * TT * TT;

    const int am = tid >> 2;
    const int ak = (tid & 3) * 4;

    float acc[4][4] = {};

    const float* Qptr = Qb + (size_t)tBlk * DD;
    const float* Kptr = Kb + (size_t)sBlk * DD;

    for (int k0 = 0; k0 < DD; k0 += 16) {
        float4 qv = *(const float4*)(Qptr + (size_t)am * DD + (k0 + ak));
        As[ak + 0][am] = qv.x;
        As[ak + 1][am] = qv.y;
        As[ak + 2][am] = qv.z;
        As[ak + 3][am] = qv.w;

        float4 kv = *(const float4*)(Kptr + (size_t)am * DD + (k0 + ak));
        Bs[ak + 0][am] = kv.x;
        Bs[ak + 1][am] = kv.y;
        Bs[ak + 2][am] = kv.z;
        Bs[ak + 3][am] = kv.w;

        __syncthreads();

        #pragma unroll
        for (int k = 0; k < 16; k++) {
            float af[4], bf[4];
            #pragma unroll
            for (int i = 0; i < 4; i++) af[i] = As[k][ty + 16 * i];
            #pragma unroll
            for (int j = 0; j < 4; j++) bf[j] = Bs[k][tx + 16 * j];
            #pragma unroll
            for (int i = 0; i < 4; i++)
                #pragma unroll
                for (int j = 0; j < 4; j++)
                    acc[i][j] += af[i] * bf[j];
        }
        __syncthreads();
    }

    #pragma unroll
    for (int i = 0; i < 4; i++) {
        const int t = tBlk + ty + 16 * i;
        #pragma unroll
        for (int j = 0; j < 4; j++) {
            const int s = sBlk + tx + 16 * j;
            Sb[(size_t)t * TT + s] = acc[i][j] * scale;
        }
    }
}

// ---------------------------------------------------------------------------
// Causal row softmax, in place, one CTA per (b,t) row. Row held in smem:
// one global read + one global write. Zero-pads s in (t, next 64-boundary)
// so the causal P@V GEMM needs no masking.
// ---------------------------------------------------------------------------
__global__ void __launch_bounds__(256) softmax_causal(float* __restrict__ S)
{
    const int r = blockIdx.x;      // 0..B*T-1
    const int b = r / TT;
    const int t = r % TT;
    float* p = S + (size_t)b * TT * TT + (size_t)t * TT;
    const int n = t + 1;

    __shared__ float buf[TT];
    __shared__ float red[256];
    const int tid = threadIdx.x;

    float m = -1e30f;
    for (int i = tid; i < n; i += 256) {
        float v = p[i];
        buf[i] = v;
        m = fmaxf(m, v);
    }
    red[tid] = m;
    __syncthreads();
    for (int s = 128; s > 0; s >>= 1) {
        if (tid < s) red[tid] = fmaxf(red[tid], red[tid + s]);
        __syncthreads();
    }
    m = red[0];
    __syncthreads();

    float sum = 0.0f;
    for (int i = tid; i < n; i += 256) {
        float e = __expf(buf[i] - m);
        buf[i] = e;
        sum += e;
    }
    red[tid] = sum;
    __syncthreads();
    for (int s = 128; s > 0; s >>= 1) {
        if (tid < s) red[tid] += red[tid + s];
        __syncthreads();
    }
    const float inv = 1.0f / red[0];

    for (int i = tid; i < n; i += 256) p[i] = buf[i] * inv;

    // zero the diagonal-block tail so P@V can run whole 64-wide K-tiles
    const int nPad = ((t >> 6) + 1) << 6;
    for (int i = n + tid; i < nPad; i += 256) p[i] = 0.0f;
}

// ---------------------------------------------------------------------------
// Launch
// ---------------------------------------------------------------------------
extern "C" void kernel_launch(void* const* d_in, const int* in_sizes, int n_in,
                              void* d_out, int out_size)
{
    const float* x  = (const float*)d_in[0];
    const float* Wq = (const float*)d_in[1];
    const float* bq = (const float*)d_in[2];
    const float* Wk = (const float*)d_in[3];
    const float* bk = (const float*)d_in[4];
    const float* Wv = (const float*)d_in[5];
    const float* bv = (const float*)d_in[6];
    const float* Wh = (const float*)d_in[7];
    const float* bh = (const float*)d_in[8];
    float* out = (float*)d_out;

    float *Qp, *Kp, *Vp, *Op, *Sp;
    cudaGetSymbolAddress((void**)&Qp, g_Q);
    cudaGetSymbolAddress((void**)&Kp, g_K);
    cudaGetSymbolAddress((void**)&Vp, g_V);
    cudaGetSymbolAddress((void**)&Op, g_O);
    cudaGetSymbolAddress((void**)&Sp, g_S);

    const float scale = 1.0f / sqrtf((float)DD);   // 1/32

    // 1-3) Q/K/V projections: [8192,1024] @ [1024,1024] + bias
    dim3 gProj(DD / 64, NROWS / 64, 1);
    gemm_nn<false, true><<<gProj, 256>>>(x, Wq, bq, Qp, DD, DD, DD, DD, 0, 0, 0);
    gemm_nn<false, true><<<gProj, 256>>>(x, Wk, bk, Kp, DD, DD, DD, DD, 0, 0, 0);
    gemm_nn<false, true><<<gProj, 256>>>(x, Wv, bv, Vp, DD, DD, DD, DD, 0, 0, 0);

    // 4) scores = scale * Q @ K^T (lower-triangle blocks only)
    dim3 gScore(TT / 64, TT / 64, BB);
    gemm_nt_causal<<<gScore, 256>>>(Qp, Kp, Sp, scale);

    // 5) causal softmax in place
    softmax_causal<<<NROWS, 256>>>(Sp);

    // 6) O = P @ V, K-loop truncated per row-block (causal)
    dim3 gPV(DD / 64, TT / 64, BB);
    gemm_nn<true, false><<<gPV, 256>>>(Sp, Vp, nullptr, Op, TT, TT, DD, DD,
                                       (size_t)TT * TT, (size_t)TT * DD,
                                       (size_t)TT * DD);

    // 7) out = O @ Wh + bh
    gemm_nn<false, true><<<gProj, 256>>>(Op, Wh, bh, out, DD, DD, DD, DD, 0, 0, 0);
}

// round 3
// speedup vs baseline: 2.6911x; 2.6911x over previous
#include <cuda_runtime.h>
#include <cuda_bf16.h>
#include <math.h>
#include <stdint.h>

typedef __nv_bfloat16 bf16;

// Problem shape (fixed)
#define BB 4
#define TT 2048
#define DD 1024
#define NROWS (BB * TT)   // 8192

// ---------------------------------------------------------------------------
// Scratch (device globals — allocation is forbidden)
// ---------------------------------------------------------------------------
__device__ bf16  g_xh[(size_t)NROWS * DD];
__device__ bf16  g_xl[(size_t)NROWS * DD];
__device__ bf16  g_Wqh[(size_t)DD * DD], g_Wql[(size_t)DD * DD];
__device__ bf16  g_Wkh[(size_t)DD * DD], g_Wkl[(size_t)DD * DD];
__device__ bf16  g_Wvh[(size_t)DD * DD], g_Wvl[(size_t)DD * DD];
__device__ bf16  g_Whh[(size_t)DD * DD], g_Whl[(size_t)DD * DD];
__device__ bf16  g_Qh[(size_t)NROWS * DD], g_Ql[(size_t)NROWS * DD];
__device__ bf16  g_Kh[(size_t)NROWS * DD], g_Kl[(size_t)NROWS * DD];
__device__ float g_V[(size_t)NROWS * DD];
__device__ bf16  g_Vth[(size_t)NROWS * DD], g_Vtl[(size_t)NROWS * DD]; // [B][D][T]
__device__ float g_S[(size_t)BB * TT * TT];
__device__ bf16  g_Ph[(size_t)BB * TT * TT], g_Pl[(size_t)BB * TT * TT];
__device__ bf16  g_Oh[(size_t)NROWS * DD], g_Ol[(size_t)NROWS * DD];

// ---------------------------------------------------------------------------
// Low-level helpers (all baseline PTX — valid at compute_103)
// ---------------------------------------------------------------------------
__device__ __forceinline__ uint32_t smem_u32(const void* p) {
    uint32_t a;
    asm("{ .reg .u64 t; cvta.to.shared.u64 t, %1; cvt.u32.u64 %0, t; }" : "=r"(a) : "l"(p));
    return a;
}

__device__ __forceinline__ void ldsm_x4(uint32_t* r, uint32_t addr) {
    asm volatile("ldmatrix.sync.aligned.m8n8.x4.shared.b16 {%0,%1,%2,%3}, [%4];"
                 : "=r"(r[0]), "=r"(r[1]), "=r"(r[2]), "=r"(r[3]) : "r"(addr));
}

__device__ __forceinline__ void mma16816(float* c, const uint32_t* a, const uint32_t* b) {
    asm volatile(
        "mma.sync.aligned.m16n8k16.row.col.f32.bf16.bf16.f32 "
        "{%0,%1,%2,%3}, {%4,%5,%6,%7}, {%8,%9}, {%0,%1,%2,%3};"
        : "+f"(c[0]), "+f"(c[1]), "+f"(c[2]), "+f"(c[3])
        : "r"(a[0]), "r"(a[1]), "r"(a[2]), "r"(a[3]), "r"(b[0]), "r"(b[1]));
}

// ---------------------------------------------------------------------------
// Tensor-core GEMM:  C[m,n] = sum_k A[m,k] * B[n,k]   (A,B as hi/lo bf16 pairs)
// 128x128 CTA tile, BK=32, 8 warps (2x4), warp tile 64x32, m16n8k16 MMA.
// 3-term split: Ah*Bh + Ah*Bl + Al*Bh  (fp32 accumulate).
// ---------------------------------------------------------------------------
#define ROW_B   80                    // 32 bf16 = 64B data, padded to 80B
#define TILE_B  (128 * ROW_B)         // 10240 B
#define STAGE_B (4 * TILE_B)          // Ah, Al, Bh, Bl
#define GEMM_SMEM (2 * STAGE_B)       // 81920 B

__device__ __forceinline__ void load_tile_async(uint32_t sdst, const bf16* __restrict__ g,
                                                int rowBase, int ld, int kBase, int tid) {
    #pragma unroll
    for (int p = 0; p < 2; p++) {
        int c = tid + p * 256;           // 0..511
        int r = c >> 2;                  // row 0..127
        int ch = c & 3;                  // 16B chunk 0..3
        uint32_t dst = sdst + (uint32_t)(r * ROW_B + ch * 16);
        const char* src = (const char*)(g + (size_t)(rowBase + r) * ld + kBase) + ch * 16;
        asm volatile("cp.async.cg.shared.global [%0], [%1], 16;" :: "r"(dst), "l"(src));
    }
}

template <bool BIAS, bool WF32, bool WSPLIT, bool CAUSAL, bool TRUNC>
__global__ void __launch_bounds__(256) gemm_tc(
    const bf16* __restrict__ Ah, const bf16* __restrict__ Al,
    const bf16* __restrict__ Bh, const bf16* __restrict__ Bl,
    const float* __restrict__ bias,
    float* __restrict__ C, bf16* __restrict__ Ch, bf16* __restrict__ Cl,
    int K, int ldA, int ldB, int ldC, float scale,
    size_t aBatch, size_t bBatch, size_t cBatch)
{
    extern __shared__ char smem[];
    const int nBase = blockIdx.x * 128;
    const int mBase = blockIdx.y * 128;
    if (CAUSAL && nBase >= mBase + 128) return;   // fully-masked tile

    const uint32_t sb = smem_u32(smem);
    const int tid = threadIdx.x;
    const int wid = tid >> 5;
    const int lane = tid & 31;
    const int wm = wid >> 2;        // 0..1 -> m offset wm*64
    const int wn = wid & 3;         // 0..3 -> n offset wn*32

    const bf16* ah = Ah + (size_t)blockIdx.z * aBatch;
    const bf16* al = Al + (size_t)blockIdx.z * aBatch;
    const bf16* bh = Bh + (size_t)blockIdx.z * bBatch;
    const bf16* bl = Bl + (size_t)blockIdx.z * bBatch;

    int kEnd = K;
    if (TRUNC) { int ke = mBase + 128; kEnd = ke < K ? ke : K; }
    const int nch = kEnd >> 5;      // BK = 32

    // per-thread ldmatrix offsets
    const uint32_t aOff = (uint32_t)((lane & 15) * ROW_B + (lane >> 4) * 16);
    const uint32_t bOff = (uint32_t)(((lane & 7) + 8 * (lane >> 4)) * ROW_B + ((lane >> 3) & 1) * 16);

    float acc[4][4][4];
    #pragma unroll
    for (int i = 0; i < 4; i++)
        #pragma unroll
        for (int j = 0; j < 4; j++)
            #pragma unroll
            for (int k = 0; k < 4; k++) acc[i][j][k] = 0.0f;

    // prologue: stage 0
    {
        uint32_t s0 = sb;
        load_tile_async(s0 + 0 * TILE_B, ah, mBase, ldA, 0, tid);
        load_tile_async(s0 + 1 * TILE_B, al, mBase, ldA, 0, tid);
        load_tile_async(s0 + 2 * TILE_B, bh, nBase, ldB, 0, tid);
        load_tile_async(s0 + 3 * TILE_B, bl, nBase, ldB, 0, tid);
        asm volatile("cp.async.commit_group;" ::: "memory");
    }

    for (int c = 0; c < nch; c++) {
        const int s = c & 1;
        asm volatile("cp.async.wait_group 0;" ::: "memory");
        __syncthreads();

        // prefetch next chunk into the other stage
        if (c + 1 < nch) {
            uint32_t sn = sb + (s ^ 1) * STAGE_B;
            int kb = (c + 1) * 32;
            load_tile_async(sn + 0 * TILE_B, ah, mBase, ldA, kb, tid);
            load_tile_async(sn + 1 * TILE_B, al, mBase, ldA, kb, tid);
            load_tile_async(sn + 2 * TILE_B, bh, nBase, ldB, kb, tid);
            load_tile_async(sn + 3 * TILE_B, bl, nBase, ldB, kb, tid);
            asm volatile("cp.async.commit_group;" ::: "memory");
        }

        const uint32_t st = sb + s * STAGE_B;
        const uint32_t aHB = st + 0 * TILE_B + (uint32_t)(wm * 64 * ROW_B) + aOff;
        const uint32_t aLB = st + 1 * TILE_B + (uint32_t)(wm * 64 * ROW_B) + aOff;
        const uint32_t bHB = st + 2 * TILE_B + (uint32_t)(wn * 32 * ROW_B) + bOff;
        const uint32_t bLB = st + 3 * TILE_B + (uint32_t)(wn * 32 * ROW_B) + bOff;

        #pragma unroll
        for (int ks = 0; ks < 2; ks++) {
            const uint32_t kb = (uint32_t)(ks * 32);   // 16 bf16 = 32 B
            uint32_t afh[4][4], afl[4][4];
            #pragma unroll
            for (int mf = 0; mf < 4; mf++) {
                ldsm_x4(afh[mf], aHB + (uint32_t)(mf * 16 * ROW_B) + kb);
                ldsm_x4(afl[mf], aLB + (uint32_t)(mf * 16 * ROW_B) + kb);
            }
            uint32_t bfh[4][2], bfl[4][2];
            #pragma unroll
            for (int np = 0; np < 2; np++) {
                uint32_t r4[4];
                ldsm_x4(r4, bHB + (uint32_t)(np * 16 * ROW_B) + kb);
                bfh[2 * np][0] = r4[0]; bfh[2 * np][1] = r4[1];
                bfh[2 * np + 1][0] = r4[2]; bfh[2 * np + 1][1] = r4[3];
                ldsm_x4(r4, bLB + (uint32_t)(np * 16 * ROW_B) + kb);
                bfl[2 * np][0] = r4[0]; bfl[2 * np][1] = r4[1];
                bfl[2 * np + 1][0] = r4[2]; bfl[2 * np + 1][1] = r4[3];
            }
            #pragma unroll
            for (int mf = 0; mf < 4; mf++)
                #pragma unroll
                for (int nf = 0; nf < 4; nf++) {
                    mma16816(acc[mf][nf], afh[mf], bfh[nf]);
                    mma16816(acc[mf][nf], afh[mf], bfl[nf]);
                    mma16816(acc[mf][nf], afl[mf], bfh[nf]);
                }
        }
        __syncthreads();
    }

    // epilogue
    float*  Cp  = WF32   ? (C  + (size_t)blockIdx.z * cBatch) : nullptr;
    bf16*   Chp = WSPLIT ? (Ch + (size_t)blockIdx.z * cBatch) : nullptr;
    bf16*   Clp = WSPLIT ? (Cl + (size_t)blockIdx.z * cBatch) : nullptr;
    const int gid = lane >> 2;      // 0..7
    const int tig = lane & 3;       // 0..3
    #pragma unroll
    for (int mf = 0; mf < 4; mf++) {
        const int row0 = mBase + wm * 64 + mf * 16 + gid;
        #pragma unroll
        for (int nf = 0; nf < 4; nf++) {
            const int col0 = nBase + wn * 32 + nf * 8 + 2 * tig;
            #pragma unroll
            for (int h = 0; h < 2; h++) {            // h=0: row0, h=1: row0+8
                const int m = row0 + 8 * h;
                #pragma unroll
                for (int w = 0; w < 2; w++) {
                    const int n = col0 + w;
                    float v = acc[mf][nf][2 * h + w] * scale;
                    if (BIAS) v += bias[n];
                    if (WF32) Cp[(size_t)m * ldC + n] = v;
                    if (WSPLIT) {
                        bf16 hi = __float2bfloat16(v);
                        Chp[(size_t)m * ldC + n] = hi;
                        Clp[(size_t)m * ldC + n] = __float2bfloat16(v - __bfloat162float(hi));
                    }
                }
            }
        }
    }
}

// ---------------------------------------------------------------------------
// Prep kernels
// ---------------------------------------------------------------------------
__global__ void __launch_bounds__(256) convert_split(const float* __restrict__ in,
                                                     bf16* __restrict__ oh, bf16* __restrict__ ol,
                                                     size_t n)
{
    size_t i = (size_t)blockIdx.x * 256 + threadIdx.x;
    size_t stride = (size_t)gridDim.x * 256;
    for (; i < n; i += stride) {
        float v = in[i];
        bf16 h = __float2bfloat16(v);
        oh[i] = h;
        ol[i] = __float2bfloat16(v - __bfloat162float(h));
    }
}

// out[c][r] = in[r][c]  (per batch z), output as hi/lo bf16
__global__ void __launch_bounds__(256) transpose_split(const float* __restrict__ in,
                                                       bf16* __restrict__ oh, bf16* __restrict__ ol,
                                                       int R, int C, size_t inB, size_t outB)
{
    __shared__ float t[32][33];
    const float* ib = in + (size_t)blockIdx.z * inB;
    bf16* ohB = oh + (size_t)blockIdx.z * outB;
    bf16* olB = ol + (size_t)blockIdx.z * outB;
    const int x = blockIdx.x * 32;
    const int y = blockIdx.y * 32;
    const int tx = threadIdx.x & 31;
    const int ty = threadIdx.x >> 5;   // 0..7
    #pragma unroll
    for (int i = 0; i < 32; i += 8)
        t[ty + i][tx] = ib[(size_t)(y + ty + i) * C + (x + tx)];
    __syncthreads();
    #pragma unroll
    for (int i = 0; i < 32; i += 8) {
        float v = t[tx][ty + i];
        size_t o = (size_t)(x + ty + i) * R + (y + tx);
        bf16 h = __float2bfloat16(v);
        ohB[o] = h;
        olB[o] = __float2bfloat16(v - __bfloat162float(h));
    }
}

// ---------------------------------------------------------------------------
// Causal softmax: S fp32 row -> P hi/lo bf16, zero-padded to 128-boundary.
// ---------------------------------------------------------------------------
__global__ void __launch_bounds__(256) softmax_causal(const float* __restrict__ S,
                                                      bf16* __restrict__ Ph, bf16* __restrict__ Pl)
{
    const int r = blockIdx.x;
    const int b = r / TT;
    const int t = r % TT;
    const size_t rowOff = (size_t)b * TT * TT + (size_t)t * TT;
    const float* p = S + rowOff;
    bf16* ph = Ph + rowOff;
    bf16* pl = Pl + rowOff;
    const int n = t + 1;

    __shared__ float buf[TT];
    __shared__ float red[256];
    const int tid = threadIdx.x;

    float m = -1e30f;
    for (int i = tid; i < n; i += 256) {
        float v = p[i];
        buf[i] = v;
        m = fmaxf(m, v);
    }
    red[tid] = m;
    __syncthreads();
    for (int s = 128; s > 0; s >>= 1) {
        if (tid < s) red[tid] = fmaxf(red[tid], red[tid + s]);
        __syncthreads();
    }
    m = red[0];
    __syncthreads();

    float sum = 0.0f;
    for (int i = tid; i < n; i += 256) {
        float e = __expf(buf[i] - m);
        buf[i] = e;
        sum += e;
    }
    red[tid] = sum;
    __syncthreads();
    for (int s = 128; s > 0; s >>= 1) {
        if (tid < s) red[tid] += red[tid + s];
        __syncthreads();
    }
    const float inv = 1.0f / red[0];

    for (int i = tid; i < n; i += 256) {
        float v = buf[i] * inv;
        bf16 h = __float2bfloat16(v);
        ph[i] = h;
        pl[i] = __float2bfloat16(v - __bfloat162float(h));
    }
    // zero-pad to the 128 tile boundary so P@V can run full K tiles
    const int nPad = ((t >> 7) + 1) << 7;
    for (int i = n + tid; i < nPad; i += 256) {
        ph[i] = __float2bfloat16(0.0f);
        pl[i] = __float2bfloat16(0.0f);
    }
}

// ---------------------------------------------------------------------------
// Launch
// ---------------------------------------------------------------------------
extern "C" void kernel_launch(void* const* d_in, const int* in_sizes, int n_in,
                              void* d_out, int out_size)
{
    const float* x  = (const float*)d_in[0];
    const float* Wq = (const float*)d_in[1];
    const float* bq = (const float*)d_in[2];
    const float* Wk = (const float*)d_in[3];
    const float* bk = (const float*)d_in[4];
    const float* Wv = (const float*)d_in[5];
    const float* bv = (const float*)d_in[6];
    const float* Wh = (const float*)d_in[7];
    const float* bh = (const float*)d_in[8];
    float* out = (float*)d_out;

    bf16 *xh, *xl, *Wqh, *Wql, *Wkh, *Wkl, *Wvh, *Wvl, *Whh, *Whl;
    bf16 *Qh, *Ql, *Kh, *Kl, *Vth, *Vtl, *Ph, *Pl, *Oh, *Ol;
    float *Vp, *Sp;
    cudaGetSymbolAddress((void**)&xh, g_xh);   cudaGetSymbolAddress((void**)&xl, g_xl);
    cudaGetSymbolAddress((void**)&Wqh, g_Wqh); cudaGetSymbolAddress((void**)&Wql, g_Wql);
    cudaGetSymbolAddress((void**)&Wkh, g_Wkh); cudaGetSymbolAddress((void**)&Wkl, g_Wkl);
    cudaGetSymbolAddress((void**)&Wvh, g_Wvh); cudaGetSymbolAddress((void**)&Wvl, g_Wvl);
    cudaGetSymbolAddress((void**)&Whh, g_Whh); cudaGetSymbolAddress((void**)&Whl, g_Whl);
    cudaGetSymbolAddress((void**)&Qh, g_Qh);   cudaGetSymbolAddress((void**)&Ql, g_Ql);
    cudaGetSymbolAddress((void**)&Kh, g_Kh);   cudaGetSymbolAddress((void**)&Kl, g_Kl);
    cudaGetSymbolAddress((void**)&Vp, g_V);
    cudaGetSymbolAddress((void**)&Vth, g_Vth); cudaGetSymbolAddress((void**)&Vtl, g_Vtl);
    cudaGetSymbolAddress((void**)&Sp, g_S);
    cudaGetSymbolAddress((void**)&Ph, g_Ph);   cudaGetSymbolAddress((void**)&Pl, g_Pl);
    cudaGetSymbolAddress((void**)&Oh, g_Oh);   cudaGetSymbolAddress((void**)&Ol, g_Ol);

    cudaFuncSetAttribute(gemm_tc<true,  false, true,  false, false>, cudaFuncAttributeMaxDynamicSharedMemorySize, GEMM_SMEM);
    cudaFuncSetAttribute(gemm_tc<true,  true,  false, false, false>, cudaFuncAttributeMaxDynamicSharedMemorySize, GEMM_SMEM);
    cudaFuncSetAttribute(gemm_tc<false, true,  false, true,  false>, cudaFuncAttributeMaxDynamicSharedMemorySize, GEMM_SMEM);
    cudaFuncSetAttribute(gemm_tc<false, false, true,  false, true >, cudaFuncAttributeMaxDynamicSharedMemorySize, GEMM_SMEM);

    const float scale = 1.0f / 32.0f;   // 1/sqrt(1024)

    // --- prep: split x; transpose+split weights ---
    convert_split<<<2048, 256>>>(x, xh, xl, (size_t)NROWS * DD);
    dim3 gW(DD / 32, DD / 32, 1);
    transpose_split<<<gW, 256>>>(Wq, Wqh, Wql, DD, DD, 0, 0);
    transpose_split<<<gW, 256>>>(Wk, Wkh, Wkl, DD, DD, 0, 0);
    transpose_split<<<gW, 256>>>(Wv, Wvh, Wvl, DD, DD, 0, 0);
    transpose_split<<<gW, 256>>>(Wh, Whh, Whl, DD, DD, 0, 0);

    // --- Q/K projections (write hi/lo directly), V projection (fp32) ---
    dim3 gProj(DD / 128, NROWS / 128, 1);
    gemm_tc<true, false, true, false, false><<<gProj, 256, GEMM_SMEM>>>(
        xh, xl, Wqh, Wql, bq, nullptr, Qh, Ql, DD, DD, DD, DD, 1.0f, 0, 0, 0);
    gemm_tc<true, false, true, false, false><<<gProj, 256, GEMM_SMEM>>>(
        xh, xl, Wkh, Wkl, bk, nullptr, Kh, Kl, DD, DD, DD, DD, 1.0f, 0, 0, 0);
    gemm_tc<true, true, false, false, false><<<gProj, 256, GEMM_SMEM>>>(
        xh, xl, Wvh, Wvl, bv, Vp, nullptr, nullptr, DD, DD, DD, DD, 1.0f, 0, 0, 0);

    // --- V transpose+split: [T,D] -> [D,T] per batch ---
    dim3 gVt(DD / 32, TT / 32, BB);
    transpose_split<<<gVt, 256>>>(Vp, Vth, Vtl, TT, DD, (size_t)TT * DD, (size_t)TT * DD);

    // --- scores = (Q K^T) / 32, causal-skipped tiles ---
    dim3 gScore(TT / 128, TT / 128, BB);
    gemm_tc<false, true, false, true, false><<<gScore, 256, GEMM_SMEM>>>(
        Qh, Ql, Kh, Kl, nullptr, Sp, nullptr, nullptr, DD, DD, DD, TT, scale,
        (size_t)TT * DD, (size_t)TT * DD, (size_t)TT * TT);

    // --- softmax -> P hi/lo (zero-padded to 128 boundary) ---
    softmax_causal<<<NROWS, 256>>>(Sp, Ph, Pl);

    // --- O = P V (K truncated per row tile), write hi/lo ---
    dim3 gPV(DD / 128, TT / 128, BB);
    gemm_tc<false, false, true, false, true><<<gPV, 256, GEMM_SMEM>>>(
        Ph, Pl, Vth, Vtl, nullptr, nullptr, Oh, Ol, TT, TT, TT, DD, 1.0f,
        (size_t)TT * TT, (size_t)TT * DD, (size_t)TT * DD);

    // --- out = O Wh + bh ---
    gemm_tc<true, true, false, false, false><<<gProj, 256, GEMM_SMEM>>>(
        Oh, Ol, Whh, Whl, bh, out, nullptr, nullptr, DD, DD, DD, DD, 1.0f, 0, 0, 0);
}

// round 4
// speedup vs baseline: 3.0368x; 1.1285x over previous
#include <cuda_runtime.h>
#include <cuda_bf16.h>
#include <math.h>
#include <stdint.h>

typedef __nv_bfloat16 bf16;

// Problem shape (fixed)
#define BB 4
#define TT 2048
#define DD 1024
#define NROWS (BB * TT)   // 8192

// ---------------------------------------------------------------------------
// Scratch (device globals — allocation is forbidden)
// ---------------------------------------------------------------------------
__device__ bf16  g_xh[(size_t)NROWS * DD];
__device__ bf16  g_xl[(size_t)NROWS * DD];
__device__ bf16  g_Wqh[(size_t)DD * DD], g_Wql[(size_t)DD * DD];
__device__ bf16  g_Wkh[(size_t)DD * DD], g_Wkl[(size_t)DD * DD];
__device__ bf16  g_Wvh[(size_t)DD * DD], g_Wvl[(size_t)DD * DD];
__device__ bf16  g_Whh[(size_t)DD * DD], g_Whl[(size_t)DD * DD];
__device__ bf16  g_Qh[(size_t)NROWS * DD], g_Ql[(size_t)NROWS * DD];
__device__ bf16  g_Kh[(size_t)NROWS * DD], g_Kl[(size_t)NROWS * DD];
__device__ float g_V[(size_t)NROWS * DD];
__device__ bf16  g_Vth[(size_t)NROWS * DD], g_Vtl[(size_t)NROWS * DD]; // [B][D][T]
__device__ float g_S[(size_t)BB * TT * TT];
__device__ bf16  g_Ph[(size_t)BB * TT * TT], g_Pl[(size_t)BB * TT * TT];
__device__ bf16  g_Oh[(size_t)NROWS * DD], g_Ol[(size_t)NROWS * DD];

// ---------------------------------------------------------------------------
// Low-level helpers (baseline PTX — valid at compute_103)
// ---------------------------------------------------------------------------
__device__ __forceinline__ uint32_t smem_u32(const void* p) {
    uint32_t a;
    asm("{ .reg .u64 t; cvta.to.shared.u64 t, %1; cvt.u32.u64 %0, t; }" : "=r"(a) : "l"(p));
    return a;
}

__device__ __forceinline__ void ldsm_x4(uint32_t* r, uint32_t addr) {
    asm volatile("ldmatrix.sync.aligned.m8n8.x4.shared.b16 {%0,%1,%2,%3}, [%4];"
                 : "=r"(r[0]), "=r"(r[1]), "=r"(r[2]), "=r"(r[3]) : "r"(addr));
}

__device__ __forceinline__ void mma16816(float* c, const uint32_t* a, const uint32_t* b) {
    asm volatile(
        "mma.sync.aligned.m16n8k16.row.col.f32.bf16.bf16.f32 "
        "{%0,%1,%2,%3}, {%4,%5,%6,%7}, {%8,%9}, {%0,%1,%2,%3};"
        : "+f"(c[0]), "+f"(c[1]), "+f"(c[2]), "+f"(c[3])
        : "r"(a[0]), "r"(a[1]), "r"(a[2]), "r"(a[3]), "r"(b[0]), "r"(b[1]));
}

__device__ __forceinline__ __nv_bfloat162 split_hi2(float v0, float v1, float& r0, float& r1) {
    bf16 h0 = __float2bfloat16(v0);
    bf16 h1 = __float2bfloat16(v1);
    r0 = v0 - __bfloat162float(h0);
    r1 = v1 - __bfloat162float(h1);
    return __nv_bfloat162(h0, h1);
}

// ---------------------------------------------------------------------------
// Tensor-core GEMM:  C[m,n] = sum_k A[m,k] * B[n,k]   (A,B as hi/lo bf16 pairs)
// 128x128 CTA tile, BK=32, 8 warps (2x4), warp tile 64x32, m16n8k16 MMA.
// 3-term split: Ah*Bh + Ah*Bl + Al*Bh  (fp32 accumulate).
// 3-stage cp.async pipeline; one barrier per chunk; frag double-buffering.
// ---------------------------------------------------------------------------
#define ROW_B   80                    // 32 bf16 = 64B data, padded to 80B
#define TILE_B  (128 * ROW_B)         // 10240 B
#define STAGE_B (4 * TILE_B)          // Ah, Al, Bh, Bl
#define STAGES  3
#define GEMM_SMEM (STAGES * STAGE_B)  // 122880 B

__device__ __forceinline__ void load_tile_async(uint32_t sdst, const bf16* __restrict__ g,
                                                int rowBase, int ld, int kBase, int tid) {
    #pragma unroll
    for (int p = 0; p < 2; p++) {
        int c = tid + p * 256;           // 0..511
        int r = c >> 2;                  // row 0..127
        int ch = c & 3;                  // 16B chunk 0..3
        uint32_t dst = sdst + (uint32_t)(r * ROW_B + ch * 16);
        const char* src = (const char*)(g + (size_t)(rowBase + r) * ld + kBase) + ch * 16;
        asm volatile("cp.async.cg.shared.global [%0], [%1], 16;" :: "r"(dst), "l"(src));
    }
}

template <bool BIAS, bool WF32, bool WSPLIT, bool CAUSAL, bool TRUNC>
__global__ void __launch_bounds__(256) gemm_tc(
    const bf16* __restrict__ Ah, const bf16* __restrict__ Al,
    const bf16* __restrict__ Bh, const bf16* __restrict__ Bl,
    const float* __restrict__ bias,
    float* __restrict__ C, bf16* __restrict__ Ch, bf16* __restrict__ Cl,
    int K, int ldA, int ldB, int ldC, float scale,
    size_t aBatch, size_t bBatch, size_t cBatch)
{
    extern __shared__ char smem[];
    const int nBase = blockIdx.x * 128;
    const int mBase = blockIdx.y * 128;
    if (CAUSAL && nBase >= mBase + 128) return;   // fully-masked tile

    const uint32_t sb = smem_u32(smem);
    const int tid = threadIdx.x;
    const int wid = tid >> 5;
    const int lane = tid & 31;
    const int wm = wid >> 2;        // 0..1 -> m offset wm*64
    const int wn = wid & 3;         // 0..3 -> n offset wn*32

    const bf16* ah = Ah + (size_t)blockIdx.z * aBatch;
    const bf16* al = Al + (size_t)blockIdx.z * aBatch;
    const bf16* bh = Bh + (size_t)blockIdx.z * bBatch;
    const bf16* bl = Bl + (size_t)blockIdx.z * bBatch;

    int kEnd = K;
    if (TRUNC) { int ke = mBase + 128; kEnd = ke < K ? ke : K; }
    const int nch = kEnd >> 5;      // BK = 32  (always >= 4 here)

    // per-thread ldmatrix offsets
    const uint32_t aOff = (uint32_t)((lane & 15) * ROW_B + (lane >> 4) * 16);
    const uint32_t bOff = (uint32_t)(((lane & 7) + 8 * (lane >> 4)) * ROW_B + ((lane >> 3) & 1) * 16);
    const uint32_t aWarp = (uint32_t)(wm * 64 * ROW_B) + aOff;
    const uint32_t bWarp = (uint32_t)(wn * 32 * ROW_B) + bOff;

    float acc[4][4][4];
    #pragma unroll
    for (int i = 0; i < 4; i++)
        #pragma unroll
        for (int j = 0; j < 4; j++)
            #pragma unroll
            for (int k = 0; k < 4; k++) acc[i][j][k] = 0.0f;

    // prologue: chunks 0 and 1 into stages 0 and 1 (two commit groups)
    {
        load_tile_async(sb + 0 * TILE_B, ah, mBase, ldA, 0, tid);
        load_tile_async(sb + 1 * TILE_B, al, mBase, ldA, 0, tid);
        load_tile_async(sb + 2 * TILE_B, bh, nBase, ldB, 0, tid);
        load_tile_async(sb + 3 * TILE_B, bl, nBase, ldB, 0, tid);
        asm volatile("cp.async.commit_group;" ::: "memory");
        uint32_t s1 = sb + STAGE_B;
        if (nch > 1) {
            load_tile_async(s1 + 0 * TILE_B, ah, mBase, ldA, 32, tid);
            load_tile_async(s1 + 1 * TILE_B, al, mBase, ldA, 32, tid);
            load_tile_async(s1 + 2 * TILE_B, bh, nBase, ldB, 32, tid);
            load_tile_async(s1 + 3 * TILE_B, bl, nBase, ldB, 32, tid);
        }
        asm volatile("cp.async.commit_group;" ::: "memory");
    }

    // fragment double-buffers (2 k16 steps per chunk)
    uint32_t afh[2][4][4], afl[2][4][4];
    uint32_t bfh[2][4][2], bfl[2][4][2];

    int stage = 0;
    for (int c = 0; c < nch; c++) {
        // chunk c's group done when <=1 group pending (group c+1 may pend)
        asm volatile("cp.async.wait_group 1;" ::: "memory");
        __syncthreads();   // stage ready + all warps done computing chunk c-1

        // prefetch chunk c+2 into the stage freed by chunk c-1
        if (c + 2 < nch) {
            int sNext = stage + 2; if (sNext >= STAGES) sNext -= STAGES;
            uint32_t sn = sb + (uint32_t)sNext * STAGE_B;
            int kb = (c + 2) * 32;
            load_tile_async(sn + 0 * TILE_B, ah, mBase, ldA, kb, tid);
            load_tile_async(sn + 1 * TILE_B, al, mBase, ldA, kb, tid);
            load_tile_async(sn + 2 * TILE_B, bh, nBase, ldB, kb, tid);
            load_tile_async(sn + 3 * TILE_B, bl, nBase, ldB, kb, tid);
        }
        asm volatile("cp.async.commit_group;" ::: "memory");   // uniform group count

        const uint32_t st = sb + (uint32_t)stage * STAGE_B;
        const uint32_t aHB = st + 0 * TILE_B + aWarp;
        const uint32_t aLB = st + 1 * TILE_B + aWarp;
        const uint32_t bHB = st + 2 * TILE_B + bWarp;
        const uint32_t bLB = st + 3 * TILE_B + bWarp;

        // load frags for ks=0 into buffer 0
        #pragma unroll
        for (int mf = 0; mf < 4; mf++) {
            ldsm_x4(afh[0][mf], aHB + (uint32_t)(mf * 16 * ROW_B));
            ldsm_x4(afl[0][mf], aLB + (uint32_t)(mf * 16 * ROW_B));
        }
        #pragma unroll
        for (int np = 0; np < 2; np++) {
            uint32_t r4[4];
            ldsm_x4(r4, bHB + (uint32_t)(np * 16 * ROW_B));
            bfh[0][2 * np][0] = r4[0]; bfh[0][2 * np][1] = r4[1];
            bfh[0][2 * np + 1][0] = r4[2]; bfh[0][2 * np + 1][1] = r4[3];
            ldsm_x4(r4, bLB + (uint32_t)(np * 16 * ROW_B));
            bfl[0][2 * np][0] = r4[0]; bfl[0][2 * np][1] = r4[1];
            bfl[0][2 * np + 1][0] = r4[2]; bfl[0][2 * np + 1][1] = r4[3];
        }

        #pragma unroll
        for (int ks = 0; ks < 2; ks++) {
            if (ks == 0) {
                // prefetch ks=1 frags into buffer 1 while MMAs of ks=0 issue
                #pragma unroll
                for (int mf = 0; mf < 4; mf++) {
                    ldsm_x4(afh[1][mf], aHB + (uint32_t)(mf * 16 * ROW_B) + 32u);
                    ldsm_x4(afl[1][mf], aLB + (uint32_t)(mf * 16 * ROW_B) + 32u);
                }
                #pragma unroll
                for (int np = 0; np < 2; np++) {
                    uint32_t r4[4];
                    ldsm_x4(r4, bHB + (uint32_t)(np * 16 * ROW_B) + 32u);
                    bfh[1][2 * np][0] = r4[0]; bfh[1][2 * np][1] = r4[1];
                    bfh[1][2 * np + 1][0] = r4[2]; bfh[1][2 * np + 1][1] = r4[3];
                    ldsm_x4(r4, bLB + (uint32_t)(np * 16 * ROW_B) + 32u);
                    bfl[1][2 * np][0] = r4[0]; bfl[1][2 * np][1] = r4[1];
                    bfl[1][2 * np + 1][0] = r4[2]; bfl[1][2 * np + 1][1] = r4[3];
                }
            }
            #pragma unroll
            for (int mf = 0; mf < 4; mf++)
                #pragma unroll
                for (int nf = 0; nf < 4; nf++) {
                    mma16816(acc[mf][nf], afh[ks][mf], bfh[ks][nf]);
                    mma16816(acc[mf][nf], afh[ks][mf], bfl[ks][nf]);
                    mma16816(acc[mf][nf], afl[ks][mf], bfh[ks][nf]);
                }
        }

        stage++; if (stage >= STAGES) stage = 0;
    }

    // epilogue — packed stores (pairs of adjacent columns)
    float*  Cp  = WF32   ? (C  + (size_t)blockIdx.z * cBatch) : nullptr;
    bf16*   Chp = WSPLIT ? (Ch + (size_t)blockIdx.z * cBatch) : nullptr;
    bf16*   Clp = WSPLIT ? (Cl + (size_t)blockIdx.z * cBatch) : nullptr;
    const int gid = lane >> 2;      // 0..7
    const int tig = lane & 3;       // 0..3
    #pragma unroll
    for (int mf = 0; mf < 4; mf++) {
        const int row0 = mBase + wm * 64 + mf * 16 + gid;
        #pragma unroll
        for (int nf = 0; nf < 4; nf++) {
            const int col0 = nBase + wn * 32 + nf * 8 + 2 * tig;   // even
            float b0 = BIAS ? bias[col0] : 0.0f;
            float b1 = BIAS ? bias[col0 + 1] : 0.0f;
            #pragma unroll
            for (int h = 0; h < 2; h++) {
                const int m = row0 + 8 * h;
                float v0 = acc[mf][nf][2 * h + 0] * scale + b0;
                float v1 = acc[mf][nf][2 * h + 1] * scale + b1;
                if (WF32) {
                    float2 f2 = make_float2(v0, v1);
                    *(float2*)&Cp[(size_t)m * ldC + col0] = f2;
                }
                if (WSPLIT) {
                    float r0, r1;
                    __nv_bfloat162 hi2 = split_hi2(v0, v1, r0, r1);
                    *(__nv_bfloat162*)&Chp[(size_t)m * ldC + col0] = hi2;
                    *(__nv_bfloat162*)&Clp[(size_t)m * ldC + col0] =
                        __nv_bfloat162(__float2bfloat16(r0), __float2bfloat16(r1));
                }
            }
        }
    }
}

// ---------------------------------------------------------------------------
// Prep kernels
// ---------------------------------------------------------------------------
__global__ void __launch_bounds__(256) convert_split(const float* __restrict__ in,
                                                     bf16* __restrict__ oh, bf16* __restrict__ ol,
                                                     size_t n4)     // n/4 float4 units
{
    const float4* in4 = (const float4*)in;
    __nv_bfloat162* oh2 = (__nv_bfloat162*)oh;
    __nv_bfloat162* ol2 = (__nv_bfloat162*)ol;
    size_t i = (size_t)blockIdx.x * 256 + threadIdx.x;
    size_t stride = (size_t)gridDim.x * 256;
    for (; i < n4; i += stride) {
        float4 v = in4[i];
        float r0, r1, r2, r3;
        __nv_bfloat162 h01 = split_hi2(v.x, v.y, r0, r1);
        __nv_bfloat162 h23 = split_hi2(v.z, v.w, r2, r3);
        oh2[2 * i]     = h01;
        oh2[2 * i + 1] = h23;
        ol2[2 * i]     = __nv_bfloat162(__float2bfloat16(r0), __float2bfloat16(r1));
        ol2[2 * i + 1] = __nv_bfloat162(__float2bfloat16(r2), __float2bfloat16(r3));
    }
}

// out[c][r] = in[r][c]  (per batch z), output as hi/lo bf16
__global__ void __launch_bounds__(256) transpose_split(const float* __restrict__ in,
                                                       bf16* __restrict__ oh, bf16* __restrict__ ol,
                                                       int R, int C, size_t inB, size_t outB)
{
    __shared__ float t[32][33];
    const float* ib = in + (size_t)blockIdx.z * inB;
    bf16* ohB = oh + (size_t)blockIdx.z * outB;
    bf16* olB = ol + (size_t)blockIdx.z * outB;
    const int x = blockIdx.x * 32;
    const int y = blockIdx.y * 32;
    const int tx = threadIdx.x & 31;
    const int ty = threadIdx.x >> 5;   // 0..7
    #pragma unroll
    for (int i = 0; i < 32; i += 8)
        t[ty + i][tx] = ib[(size_t)(y + ty + i) * C + (x + tx)];
    __syncthreads();
    #pragma unroll
    for (int i = 0; i < 32; i += 8) {
        float v = t[tx][ty + i];
        size_t o = (size_t)(x + ty + i) * R + (y + tx);
        bf16 h = __float2bfloat16(v);
        ohB[o] = h;
        olB[o] = __float2bfloat16(v - __bfloat162float(h));
    }
}

// ---------------------------------------------------------------------------
// Causal softmax: S fp32 row -> P hi/lo bf16, zero-padded to 128-boundary.
// Vectorized loads, warp-shuffle reductions (3 barriers).
// ---------------------------------------------------------------------------
__global__ void __launch_bounds__(256) softmax_causal(const float* __restrict__ S,
                                                      bf16* __restrict__ Ph, bf16* __restrict__ Pl)
{
    const int r = blockIdx.x;
    const int b = r >> 11;         // / TT
    const int t = r & (TT - 1);
    const size_t rowOff = (size_t)b * TT * TT + (size_t)t * TT;
    const float* p = S + rowOff;
    bf16* ph = Ph + rowOff;
    bf16* pl = Pl + rowOff;
    const int n = t + 1;

    __shared__ float buf[TT];
    __shared__ float wred[8];
    const int tid = threadIdx.x;
    const int lane = tid & 31;
    const int wrp = tid >> 5;

    // pass 1: load + max
    float m = -1e30f;
    const int nv = n >> 2;                    // full float4 count
    const float4* p4 = (const float4*)p;
    float4* b4 = (float4*)buf;
    for (int i = tid; i < nv; i += 256) {
        float4 v = p4[i];
        b4[i] = v;
        m = fmaxf(m, fmaxf(fmaxf(v.x, v.y), fmaxf(v.z, v.w)));
    }
    for (int i = nv * 4 + tid; i < n; i += 256) {
        float v = p[i]; buf[i] = v; m = fmaxf(m, v);
    }
    #pragma unroll
    for (int o = 16; o > 0; o >>= 1) m = fmaxf(m, __shfl_xor_sync(0xFFFFFFFFu, m, o));
    if (lane == 0) wred[wrp] = m;
    __syncthreads();
    float mAll = wred[0];
    #pragma unroll
    for (int w = 1; w < 8; w++) mAll = fmaxf(mAll, wred[w]);
    __syncthreads();                          // before wred reuse

    // pass 2: exp + sum
    float sum = 0.0f;
    for (int i = tid; i < nv; i += 256) {
        float4 v = b4[i];
        v.x = __expf(v.x - mAll); v.y = __expf(v.y - mAll);
        v.z = __expf(v.z - mAll); v.w = __expf(v.w - mAll);
        b4[i] = v;
        sum += v.x + v.y + v.z + v.w;
    }
    for (int i = nv * 4 + tid; i < n; i += 256) {
        float e = __expf(buf[i] - mAll); buf[i] = e; sum += e;
    }
    #pragma unroll
    for (int o = 16; o > 0; o >>= 1) sum += __shfl_xor_sync(0xFFFFFFFFu, sum, o);
    if (lane == 0) wred[wrp] = sum;
    __syncthreads();
    float sAll = wred[0];
    #pragma unroll
    for (int w = 1; w < 8; w++) sAll += wred[w];
    const float inv = 1.0f / sAll;

    // pass 3: write hi/lo, pairs packed
    const int n2 = n >> 1;
    __nv_bfloat162* ph2 = (__nv_bfloat162*)ph;
    __nv_bfloat162* pl2 = (__nv_bfloat162*)pl;
    for (int i = tid; i < n2; i += 256) {
        float v0 = buf[2 * i] * inv;
        float v1 = buf[2 * i + 1] * inv;
        float r0, r1;
        ph2[i] = split_hi2(v0, v1, r0, r1);
        pl2[i] = __nv_bfloat162(__float2bfloat16(r0), __float2bfloat16(r1));
    }
    if ((n & 1) && tid == 0) {
        float v = buf[n - 1] * inv;
        bf16 h = __float2bfloat16(v);
        ph[n - 1] = h;
        pl[n - 1] = __float2bfloat16(v - __bfloat162float(h));
    }
    // zero-pad to the 128 tile boundary so P@V can run full K tiles
    const int nPad = ((t >> 7) + 1) << 7;
    const bf16 z = __float2bfloat16(0.0f);
    for (int i = n + tid; i < nPad; i += 256) { ph[i] = z; pl[i] = z; }
}

// ---------------------------------------------------------------------------
// Launch
// ---------------------------------------------------------------------------
extern "C" void kernel_launch(void* const* d_in, const int* in_sizes, int n_in,
                              void* d_out, int out_size)
{
    const float* x  = (const float*)d_in[0];
    const float* Wq = (const float*)d_in[1];
    const float* bq = (const float*)d_in[2];
    const float* Wk = (const float*)d_in[3];
    const float* bk = (const float*)d_in[4];
    const float* Wv = (const float*)d_in[5];
    const float* bv = (const float*)d_in[6];
    const float* Wh = (const float*)d_in[7];
    const float* bh = (const float*)d_in[8];
    float* out = (float*)d_out;

    bf16 *xh, *xl, *Wqh, *Wql, *Wkh, *Wkl, *Wvh, *Wvl, *Whh, *Whl;
    bf16 *Qh, *Ql, *Kh, *Kl, *Vth, *Vtl, *Ph, *Pl, *Oh, *Ol;
    float *Vp, *Sp;
    cudaGetSymbolAddress((void**)&xh, g_xh);   cudaGetSymbolAddress((void**)&xl, g_xl);
    cudaGetSymbolAddress((void**)&Wqh, g_Wqh); cudaGetSymbolAddress((void**)&Wql, g_Wql);
    cudaGetSymbolAddress((void**)&Wkh, g_Wkh); cudaGetSymbolAddress((void**)&Wkl, g_Wkl);
    cudaGetSymbolAddress((void**)&Wvh, g_Wvh); cudaGetSymbolAddress((void**)&Wvl, g_Wvl);
    cudaGetSymbolAddress((void**)&Whh, g_Whh); cudaGetSymbolAddress((void**)&Whl, g_Whl);
    cudaGetSymbolAddress((void**)&Qh, g_Qh);   cudaGetSymbolAddress((void**)&Ql, g_Ql);
    cudaGetSymbolAddress((void**)&Kh, g_Kh);   cudaGetSymbolAddress((void**)&Kl, g_Kl);
    cudaGetSymbolAddress((void**)&Vp, g_V);
    cudaGetSymbolAddress((void**)&Vth, g_Vth); cudaGetSymbolAddress((void**)&Vtl, g_Vtl);
    cudaGetSymbolAddress((void**)&Sp, g_S);
    cudaGetSymbolAddress((void**)&Ph, g_Ph);   cudaGetSymbolAddress((void**)&Pl, g_Pl);
    cudaGetSymbolAddress((void**)&Oh, g_Oh);   cudaGetSymbolAddress((void**)&Ol, g_Ol);

    cudaFuncSetAttribute(gemm_tc<true,  false, true,  false, false>, cudaFuncAttributeMaxDynamicSharedMemorySize, GEMM_SMEM);
    cudaFuncSetAttribute(gemm_tc<true,  true,  false, false, false>, cudaFuncAttributeMaxDynamicSharedMemorySize, GEMM_SMEM);
    cudaFuncSetAttribute(gemm_tc<false, true,  false, true,  false>, cudaFuncAttributeMaxDynamicSharedMemorySize, GEMM_SMEM);
    cudaFuncSetAttribute(gemm_tc<false, false, true,  false, true >, cudaFuncAttributeMaxDynamicSharedMemorySize, GEMM_SMEM);

    const float scale = 1.0f / 32.0f;   // 1/sqrt(1024)

    // --- prep: split x; transpose+split weights ---
    convert_split<<<1024, 256>>>(x, xh, xl, (size_t)NROWS * DD / 4);
    dim3 gW(DD / 32, DD / 32, 1);
    transpose_split<<<gW, 256>>>(Wq, Wqh, Wql, DD, DD, 0, 0);
    transpose_split<<<gW, 256>>>(Wk, Wkh, Wkl, DD, DD, 0, 0);
    transpose_split<<<gW, 256>>>(Wv, Wvh, Wvl, DD, DD, 0, 0);
    transpose_split<<<gW, 256>>>(Wh, Whh, Whl, DD, DD, 0, 0);

    // --- Q/K projections (write hi/lo directly), V projection (fp32) ---
    dim3 gProj(DD / 128, NROWS / 128, 1);
    gemm_tc<true, false, true, false, false><<<gProj, 256, GEMM_SMEM>>>(
        xh, xl, Wqh, Wql, bq, nullptr, Qh, Ql, DD, DD, DD, DD, 1.0f, 0, 0, 0);
    gemm_tc<true, false, true, false, false><<<gProj, 256, GEMM_SMEM>>>(
        xh, xl, Wkh, Wkl, bk, nullptr, Kh, Kl, DD, DD, DD, DD, 1.0f, 0, 0, 0);
    gemm_tc<true, true, false, false, false><<<gProj, 256, GEMM_SMEM>>>(
        xh, xl, Wvh, Wvl, bv, Vp, nullptr, nullptr, DD, DD, DD, DD, 1.0f, 0, 0, 0);

    // --- V transpose+split: [T,D] -> [D,T] per batch ---
    dim3 gVt(DD / 32, TT / 32, BB);
    transpose_split<<<gVt, 256>>>(Vp, Vth, Vtl, TT, DD, (size_t)TT * DD, (size_t)TT * DD);

    // --- scores = (Q K^T) / 32, causal-skipped tiles ---
    dim3 gScore(TT / 128, TT / 128, BB);
    gemm_tc<false, true, false, true, false><<<gScore, 256, GEMM_SMEM>>>(
        Qh, Ql, Kh, Kl, nullptr, Sp, nullptr, nullptr, DD, DD, DD, TT, scale,
        (size_t)TT * DD, (size_t)TT * DD, (size_t)TT * TT);

    // --- softmax -> P hi/lo (zero-padded to 128 boundary) ---
    softmax_causal<<<NROWS, 256>>>(Sp, Ph, Pl);

    // --- O = P V (K truncated per row tile), write hi/lo ---
    dim3 gPV(DD / 128, TT / 128, BB);
    gemm_tc<false, false, true, false, true><<<gPV, 256, GEMM_SMEM>>>(
        Ph, Pl, Vth, Vtl, nullptr, nullptr, Oh, Ol, TT, TT, TT, DD, 1.0f,
        (size_t)TT * TT, (size_t)TT * DD, (size_t)TT * DD);

    // --- out = O Wh + bh ---
    gemm_tc<true, true, false, false, false><<<gProj, 256, GEMM_SMEM>>>(
        Oh, Ol, Whh, Whl, bh, out, nullptr, nullptr, DD, DD, DD, DD, 1.0f, 0, 0, 0);
}

// round 6
// speedup vs baseline: 3.2184x; 1.0598x over previous
#include <cuda_runtime.h>
#include <cuda_bf16.h>
#include <math.h>
#include <stdint.h>

typedef __nv_bfloat16 bf16;

// Problem shape (fixed)
#define BB 4
#define TT 2048
#define DD 1024
#define NROWS (BB * TT)   // 8192

// ---------------------------------------------------------------------------
// Scratch (device globals — allocation is forbidden)
// ---------------------------------------------------------------------------
__device__ bf16  g_xh[(size_t)NROWS * DD];
__device__ bf16  g_xl[(size_t)NROWS * DD];
__device__ bf16  g_Wqh[(size_t)DD * DD], g_Wql[(size_t)DD * DD];
__device__ bf16  g_Wkh[(size_t)DD * DD], g_Wkl[(size_t)DD * DD];
__device__ bf16  g_Wvh[(size_t)DD * DD], g_Wvl[(size_t)DD * DD];
__device__ bf16  g_Whh[(size_t)DD * DD], g_Whl[(size_t)DD * DD];
__device__ bf16  g_Qh[(size_t)NROWS * DD], g_Ql[(size_t)NROWS * DD];
__device__ bf16  g_Kh[(size_t)NROWS * DD], g_Kl[(size_t)NROWS * DD];
__device__ float g_V[(size_t)NROWS * DD];
__device__ bf16  g_Vth[(size_t)NROWS * DD], g_Vtl[(size_t)NROWS * DD]; // [B][D][T]
__device__ float g_S[(size_t)BB * TT * TT];
__device__ bf16  g_Ph[(size_t)BB * TT * TT], g_Pl[(size_t)BB * TT * TT];
__device__ bf16  g_Oh[(size_t)NROWS * DD], g_Ol[(size_t)NROWS * DD];

// ---------------------------------------------------------------------------
// Low-level helpers (baseline PTX — valid at compute_103)
// ---------------------------------------------------------------------------
__device__ __forceinline__ uint32_t smem_u32(const void* p) {
    uint32_t a;
    asm("{ .reg .u64 t; cvta.to.shared.u64 t, %1; cvt.u32.u64 %0, t; }" : "=r"(a) : "l"(p));
    return a;
}

__device__ __forceinline__ void ldsm_x4(uint32_t* r, uint32_t addr) {
    asm volatile("ldmatrix.sync.aligned.m8n8.x4.shared.b16 {%0,%1,%2,%3}, [%4];"
                 : "=r"(r[0]), "=r"(r[1]), "=r"(r[2]), "=r"(r[3]) : "r"(addr));
}

__device__ __forceinline__ void mma16816(float* c, const uint32_t* a, const uint32_t* b) {
    asm volatile(
        "mma.sync.aligned.m16n8k16.row.col.f32.bf16.bf16.f32 "
        "{%0,%1,%2,%3}, {%4,%5,%6,%7}, {%8,%9}, {%0,%1,%2,%3};"
        : "+f"(c[0]), "+f"(c[1]), "+f"(c[2]), "+f"(c[3])
        : "r"(a[0]), "r"(a[1]), "r"(a[2]), "r"(a[3]), "r"(b[0]), "r"(b[1]));
}

__device__ __forceinline__ __nv_bfloat162 split_hi2(float v0, float v1, float& r0, float& r1) {
    bf16 h0 = __float2bfloat16(v0);
    bf16 h1 = __float2bfloat16(v1);
    r0 = v0 - __bfloat162float(h0);
    r1 = v1 - __bfloat162float(h1);
    return __nv_bfloat162(h0, h1);
}

// ---------------------------------------------------------------------------
// Tensor-core GEMM:  C[m,n] = sum_k A[m,k] * B[n,k]   (A,B as hi/lo bf16 pairs)
// CTA tile 128x256, BK=32, 8 warps (2x4), warp tile 64x64, m16n8k16 MMA.
// 3-term split: Ah*Bh + Ah*Bl + Al*Bh  (fp32 accumulate).
// 3-stage cp.async pipeline; one barrier per chunk.
// ---------------------------------------------------------------------------
#define ROW_B   80                      // 32 bf16 = 64B data, padded to 80B
#define A_TILE_B (128 * ROW_B)          // 10240 B
#define B_TILE_B (256 * ROW_B)          // 20480 B
#define STAGE_B  (2 * A_TILE_B + 2 * B_TILE_B)   // 61440 B: Ah, Al, Bh, Bl
#define OFF_AH   0
#define OFF_AL   A_TILE_B
#define OFF_BH   (2 * A_TILE_B)
#define OFF_BL   (2 * A_TILE_B + B_TILE_B)
#define STAGES   3
#define GEMM_SMEM (STAGES * STAGE_B)    // 184320 B

template <int ROWS>
__device__ __forceinline__ void load_tile_async(uint32_t sdst, const bf16* __restrict__ g,
                                                int rowBase, int ld, int kBase, int tid) {
    #pragma unroll
    for (int p = 0; p < ROWS / 64; p++) {
        int c = tid + p * 256;           // row-chunk index
        int r = c >> 2;
        int ch = c & 3;                  // 16B chunk 0..3
        uint32_t dst = sdst + (uint32_t)(r * ROW_B + ch * 16);
        const char* src = (const char*)(g + (size_t)(rowBase + r) * ld + kBase) + ch * 16;
        asm volatile("cp.async.cg.shared.global [%0], [%1], 16;" :: "r"(dst), "l"(src));
    }
}

__device__ __forceinline__ void load_stage(uint32_t st,
                                           const bf16* ah, const bf16* al,
                                           const bf16* bh, const bf16* bl,
                                           int mBase, int nBase, int ldA, int ldB,
                                           int kb, int tid) {
    load_tile_async<128>(st + OFF_AH, ah, mBase, ldA, kb, tid);
    load_tile_async<128>(st + OFF_AL, al, mBase, ldA, kb, tid);
    load_tile_async<256>(st + OFF_BH, bh, nBase, ldB, kb, tid);
    load_tile_async<256>(st + OFF_BL, bl, nBase, ldB, kb, tid);
}

template <bool BIAS, bool WF32, bool WSPLIT, bool CAUSAL, bool TRUNC>
__global__ void __launch_bounds__(256) gemm_tc(
    const bf16* __restrict__ Ah, const bf16* __restrict__ Al,
    const bf16* __restrict__ Bh, const bf16* __restrict__ Bl,
    const float* __restrict__ bias,
    float* __restrict__ C, bf16* __restrict__ Ch, bf16* __restrict__ Cl,
    int K, int ldA, int ldB, int ldC, float scale,
    size_t aBatch, size_t bBatch, size_t cBatch)
{
    extern __shared__ char smem[];
    const int nBase = blockIdx.x * 256;
    const int mBase = blockIdx.y * 128;
    if (CAUSAL && nBase >= mBase + 128) return;   // fully-masked tile

    const uint32_t sb = smem_u32(smem);
    const int tid = threadIdx.x;
    const int wid = tid >> 5;
    const int lane = tid & 31;
    const int wm = wid >> 2;        // 0..1 -> m offset wm*64
    const int wn = wid & 3;         // 0..3 -> n offset wn*64

    const bf16* ah = Ah + (size_t)blockIdx.z * aBatch;
    const bf16* al = Al + (size_t)blockIdx.z * aBatch;
    const bf16* bh = Bh + (size_t)blockIdx.z * bBatch;
    const bf16* bl = Bl + (size_t)blockIdx.z * bBatch;

    int kEnd = K;
    if (TRUNC) { int ke = mBase + 128; kEnd = ke < K ? ke : K; }
    const int nch = kEnd >> 5;      // BK = 32 (always >= 4 here)

    // per-thread ldmatrix offsets
    const uint32_t aOff = (uint32_t)((lane & 15) * ROW_B + (lane >> 4) * 16);
    const uint32_t bOff = (uint32_t)(((lane & 7) + 8 * (lane >> 4)) * ROW_B + ((lane >> 3) & 1) * 16);
    const uint32_t aWarp = (uint32_t)(wm * 64 * ROW_B) + aOff;
    const uint32_t bWarp = (uint32_t)(wn * 64 * ROW_B) + bOff;

    float acc[4][8][4];
    #pragma unroll
    for (int i = 0; i < 4; i++)
        #pragma unroll
        for (int j = 0; j < 8; j++)
            #pragma unroll
            for (int k = 0; k < 4; k++) acc[i][j][k] = 0.0f;

    // prologue: chunks 0 and 1 into stages 0 and 1
    load_stage(sb, ah, al, bh, bl, mBase, nBase, ldA, ldB, 0, tid);
    asm volatile("cp.async.commit_group;" ::: "memory");
    if (nch > 1)
        load_stage(sb + STAGE_B, ah, al, bh, bl, mBase, nBase, ldA, ldB, 32, tid);
    asm volatile("cp.async.commit_group;" ::: "memory");

    int stage = 0;
    for (int c = 0; c < nch; c++) {
        asm volatile("cp.async.wait_group 1;" ::: "memory");
        __syncthreads();   // stage ready + all warps done with chunk c-1's stage

        // prefetch chunk c+2 into the stage freed by chunk c-1
        if (c + 2 < nch) {
            int sNext = stage + 2; if (sNext >= STAGES) sNext -= STAGES;
            load_stage(sb + (uint32_t)sNext * STAGE_B, ah, al, bh, bl,
                       mBase, nBase, ldA, ldB, (c + 2) * 32, tid);
        }
        asm volatile("cp.async.commit_group;" ::: "memory");   // uniform group count

        const uint32_t st = sb + (uint32_t)stage * STAGE_B;
        const uint32_t aHB = st + OFF_AH + aWarp;
        const uint32_t aLB = st + OFF_AL + aWarp;
        const uint32_t bHB = st + OFF_BH + bWarp;
        const uint32_t bLB = st + OFF_BL + bWarp;

        #pragma unroll
        for (int ks = 0; ks < 2; ks++) {
            const uint32_t kb = (uint32_t)(ks * 32);   // 16 bf16 = 32 B
            uint32_t afh[4][4], afl[4][4];
            #pragma unroll
            for (int mf = 0; mf < 4; mf++) {
                ldsm_x4(afh[mf], aHB + (uint32_t)(mf * 16 * ROW_B) + kb);
                ldsm_x4(afl[mf], aLB + (uint32_t)(mf * 16 * ROW_B) + kb);
            }
            uint32_t bfh[8][2], bfl[8][2];
            #pragma unroll
            for (int np = 0; np < 4; np++) {
                uint32_t r4[4];
                ldsm_x4(r4, bHB + (uint32_t)(np * 16 * ROW_B) + kb);
                bfh[2 * np][0] = r4[0]; bfh[2 * np][1] = r4[1];
                bfh[2 * np + 1][0] = r4[2]; bfh[2 * np + 1][1] = r4[3];
                ldsm_x4(r4, bLB + (uint32_t)(np * 16 * ROW_B) + kb);
                bfl[2 * np][0] = r4[0]; bfl[2 * np][1] = r4[1];
                bfl[2 * np + 1][0] = r4[2]; bfl[2 * np + 1][1] = r4[3];
            }
            #pragma unroll
            for (int mf = 0; mf < 4; mf++)
                #pragma unroll
                for (int nf = 0; nf < 8; nf++) {
                    mma16816(acc[mf][nf], afh[mf], bfh[nf]);
                    mma16816(acc[mf][nf], afh[mf], bfl[nf]);
                    mma16816(acc[mf][nf], afl[mf], bfh[nf]);
                }
        }

        stage++; if (stage >= STAGES) stage = 0;
    }

    // epilogue — packed stores (pairs of adjacent columns)
    float*  Cp  = WF32   ? (C  + (size_t)blockIdx.z * cBatch) : nullptr;
    bf16*   Chp = WSPLIT ? (Ch + (size_t)blockIdx.z * cBatch) : nullptr;
    bf16*   Clp = WSPLIT ? (Cl + (size_t)blockIdx.z * cBatch) : nullptr;
    const int gid = lane >> 2;      // 0..7
    const int tig = lane & 3;       // 0..3
    #pragma unroll
    for (int mf = 0; mf < 4; mf++) {
        const int row0 = mBase + wm * 64 + mf * 16 + gid;
        #pragma unroll
        for (int nf = 0; nf < 8; nf++) {
            const int col0 = nBase + wn * 64 + nf * 8 + 2 * tig;   // even
            float b0 = BIAS ? bias[col0] : 0.0f;
            float b1 = BIAS ? bias[col0 + 1] : 0.0f;
            #pragma unroll
            for (int h = 0; h < 2; h++) {
                const int m = row0 + 8 * h;
                float v0 = acc[mf][nf][2 * h + 0] * scale + b0;
                float v1 = acc[mf][nf][2 * h + 1] * scale + b1;
                if (WF32) {
                    float2 f2 = make_float2(v0, v1);
                    *(float2*)&Cp[(size_t)m * ldC + col0] = f2;
                }
                if (WSPLIT) {
                    float r0, r1;
                    __nv_bfloat162 hi2 = split_hi2(v0, v1, r0, r1);
                    *(__nv_bfloat162*)&Chp[(size_t)m * ldC + col0] = hi2;
                    *(__nv_bfloat162*)&Clp[(size_t)m * ldC + col0] =
                        __nv_bfloat162(__float2bfloat16(r0), __float2bfloat16(r1));
                }
            }
        }
    }
}

// ---------------------------------------------------------------------------
// Prep kernels
// ---------------------------------------------------------------------------
__global__ void __launch_bounds__(256) convert_split(const float* __restrict__ in,
                                                     bf16* __restrict__ oh, bf16* __restrict__ ol,
                                                     size_t n4)     // n/4 float4 units
{
    const float4* in4 = (const float4*)in;
    __nv_bfloat162* oh2 = (__nv_bfloat162*)oh;
    __nv_bfloat162* ol2 = (__nv_bfloat162*)ol;
    size_t i = (size_t)blockIdx.x * 256 + threadIdx.x;
    size_t stride = (size_t)gridDim.x * 256;
    for (; i < n4; i += stride) {
        float4 v = in4[i];
        float r0, r1, r2, r3;
        __nv_bfloat162 h01 = split_hi2(v.x, v.y, r0, r1);
        __nv_bfloat162 h23 = split_hi2(v.z, v.w, r2, r3);
        oh2[2 * i]     = h01;
        oh2[2 * i + 1] = h23;
        ol2[2 * i]     = __nv_bfloat162(__float2bfloat16(r0), __float2bfloat16(r1));
        ol2[2 * i + 1] = __nv_bfloat162(__float2bfloat16(r2), __float2bfloat16(r3));
    }
}

// out[c][r] = in[r][c]  (per batch z), output as hi/lo bf16
__global__ void __launch_bounds__(256) transpose_split(const float* __restrict__ in,
                                                       bf16* __restrict__ oh, bf16* __restrict__ ol,
                                                       int R, int C, size_t inB, size_t outB)
{
    __shared__ float t[32][33];
    const float* ib = in + (size_t)blockIdx.z * inB;
    bf16* ohB = oh + (size_t)blockIdx.z * outB;
    bf16* olB = ol + (size_t)blockIdx.z * outB;
    const int x = blockIdx.x * 32;
    const int y = blockIdx.y * 32;
    const int tx = threadIdx.x & 31;
    const int ty = threadIdx.x >> 5;   // 0..7
    #pragma unroll
    for (int i = 0; i < 32; i += 8)
        t[ty + i][tx] = ib[(size_t)(y + ty + i) * C + (x + tx)];
    __syncthreads();
    #pragma unroll
    for (int i = 0; i < 32; i += 8) {
        float v = t[tx][ty + i];
        size_t o = (size_t)(x + ty + i) * R + (y + tx);
        bf16 h = __float2bfloat16(v);
        ohB[o] = h;
        olB[o] = __float2bfloat16(v - __bfloat162float(h));
    }
}

// ---------------------------------------------------------------------------
// Causal softmax: S fp32 row -> P hi/lo bf16, zero-padded to 128-boundary.
// ---------------------------------------------------------------------------
__global__ void __launch_bounds__(256) softmax_causal(const float* __restrict__ S,
                                                      bf16* __restrict__ Ph, bf16* __restrict__ Pl)
{
    const int r = blockIdx.x;
    const int b = r >> 11;         // / TT
    const int t = r & (TT - 1);
    const size_t rowOff = (size_t)b * TT * TT + (size_t)t * TT;
    const float* p = S + rowOff;
    bf16* ph = Ph + rowOff;
    bf16* pl = Pl + rowOff;
    const int n = t + 1;

    __shared__ float buf[TT];
    __shared__ float wred[8];
    const int tid = threadIdx.x;
    const int lane = tid & 31;
    const int wrp = tid >> 5;

    // pass 1: load + max
    float m = -1e30f;
    const int nv = n >> 2;                    // full float4 count
    const float4* p4 = (const float4*)p;
    float4* b4 = (float4*)buf;
    for (int i = tid; i < nv; i += 256) {
        float4 v = p4[i];
        b4[i] = v;
        m = fmaxf(m, fmaxf(fmaxf(v.x, v.y), fmaxf(v.z, v.w)));
    }
    for (int i = nv * 4 + tid; i < n; i += 256) {
        float v = p[i]; buf[i] = v; m = fmaxf(m, v);
    }
    #pragma unroll
    for (int o = 16; o > 0; o >>= 1) m = fmaxf(m, __shfl_xor_sync(0xFFFFFFFFu, m, o));
    if (lane == 0) wred[wrp] = m;
    __syncthreads();
    float mAll = wred[0];
    #pragma unroll
    for (int w = 1; w < 8; w++) mAll = fmaxf(mAll, wred[w]);
    __syncthreads();                          // before wred reuse

    // pass 2: exp + sum
    float sum = 0.0f;
    for (int i = tid; i < nv; i += 256) {
        float4 v = b4[i];
        v.x = __expf(v.x - mAll); v.y = __expf(v.y - mAll);
        v.z = __expf(v.z - mAll); v.w = __expf(v.w - mAll);
        b4[i] = v;
        sum += v.x + v.y + v.z + v.w;
    }
    for (int i = nv * 4 + tid; i < n; i += 256) {
        float e = __expf(buf[i] - mAll); buf[i] = e; sum += e;
    }
    #pragma unroll
    for (int o = 16; o > 0; o >>= 1) sum += __shfl_xor_sync(0xFFFFFFFFu, sum, o);
    if (lane == 0) wred[wrp] = sum;
    __syncthreads();
    float sAll = wred[0];
    #pragma unroll
    for (int w = 1; w < 8; w++) sAll += wred[w];
    const float inv = 1.0f / sAll;

    // pass 3: write hi/lo, pairs packed
    const int n2 = n >> 1;
    __nv_bfloat162* ph2 = (__nv_bfloat162*)ph;
    __nv_bfloat162* pl2 = (__nv_bfloat162*)pl;
    for (int i = tid; i < n2; i += 256) {
        float v0 = buf[2 * i] * inv;
        float v1 = buf[2 * i + 1] * inv;
        float r0, r1;
        ph2[i] = split_hi2(v0, v1, r0, r1);
        pl2[i] = __nv_bfloat162(__float2bfloat16(r0), __float2bfloat16(r1));
    }
    if ((n & 1) && tid == 0) {
        float v = buf[n - 1] * inv;
        bf16 h = __float2bfloat16(v);
        ph[n - 1] = h;
        pl[n - 1] = __float2bfloat16(v - __bfloat162float(h));
    }
    // zero-pad to the 128 tile boundary so P@V can run full K tiles
    const int nPad = ((t >> 7) + 1) << 7;
    const bf16 z = __float2bfloat16(0.0f);
    for (int i = n + tid; i < nPad; i += 256) { ph[i] = z; pl[i] = z; }
}

// ---------------------------------------------------------------------------
// Launch
// ---------------------------------------------------------------------------
extern "C" void kernel_launch(void* const* d_in, const int* in_sizes, int n_in,
                              void* d_out, int out_size)
{
    const float* x  = (const float*)d_in[0];
    const float* Wq = (const float*)d_in[1];
    const float* bq = (const float*)d_in[2];
    const float* Wk = (const float*)d_in[3];
    const float* bk = (const float*)d_in[4];
    const float* Wv = (const float*)d_in[5];
    const float* bv = (const float*)d_in[6];
    const float* Wh = (const float*)d_in[7];
    const float* bh = (const float*)d_in[8];
    float* out = (float*)d_out;

    bf16 *xh, *xl, *Wqh, *Wql, *Wkh, *Wkl, *Wvh, *Wvl, *Whh, *Whl;
    bf16 *Qh, *Ql, *Kh, *Kl, *Vth, *Vtl, *Ph, *Pl, *Oh, *Ol;
    float *Vp, *Sp;
    cudaGetSymbolAddress((void**)&xh, g_xh);   cudaGetSymbolAddress((void**)&xl, g_xl);
    cudaGetSymbolAddress((void**)&Wqh, g_Wqh); cudaGetSymbolAddress((void**)&Wql, g_Wql);
    cudaGetSymbolAddress((void**)&Wkh, g_Wkh); cudaGetSymbolAddress((void**)&Wkl, g_Wkl);
    cudaGetSymbolAddress((void**)&Wvh, g_Wvh); cudaGetSymbolAddress((void**)&Wvl, g_Wvl);
    cudaGetSymbolAddress((void**)&Whh, g_Whh); cudaGetSymbolAddress((void**)&Whl, g_Whl);
    cudaGetSymbolAddress((void**)&Qh, g_Qh);   cudaGetSymbolAddress((void**)&Ql, g_Ql);
    cudaGetSymbolAddress((void**)&Kh, g_Kh);   cudaGetSymbolAddress((void**)&Kl, g_Kl);
    cudaGetSymbolAddress((void**)&Vp, g_V);
    cudaGetSymbolAddress((void**)&Vth, g_Vth); cudaGetSymbolAddress((void**)&Vtl, g_Vtl);
    cudaGetSymbolAddress((void**)&Sp, g_S);
    cudaGetSymbolAddress((void**)&Ph, g_Ph);   cudaGetSymbolAddress((void**)&Pl, g_Pl);
    cudaGetSymbolAddress((void**)&Oh, g_Oh);   cudaGetSymbolAddress((void**)&Ol, g_Ol);

    cudaFuncSetAttribute(gemm_tc<true,  false, true,  false, false>, cudaFuncAttributeMaxDynamicSharedMemorySize, GEMM_SMEM);
    cudaFuncSetAttribute(gemm_tc<true,  true,  false, false, false>, cudaFuncAttributeMaxDynamicSharedMemorySize, GEMM_SMEM);
    cudaFuncSetAttribute(gemm_tc<false, true,  false, true,  false>, cudaFuncAttributeMaxDynamicSharedMemorySize, GEMM_SMEM);
    cudaFuncSetAttribute(gemm_tc<false, false, true,  false, true >, cudaFuncAttributeMaxDynamicSharedMemorySize, GEMM_SMEM);

    const float scale = 1.0f / 32.0f;   // 1/sqrt(1024)

    // --- prep: split x; transpose+split weights ---
    convert_split<<<1024, 256>>>(x, xh, xl, (size_t)NROWS * DD / 4);
    dim3 gW(DD / 32, DD / 32, 1);
    transpose_split<<<gW, 256>>>(Wq, Wqh, Wql, DD, DD, 0, 0);
    transpose_split<<<gW, 256>>>(Wk, Wkh, Wkl, DD, DD, 0, 0);
    transpose_split<<<gW, 256>>>(Wv, Wvh, Wvl, DD, DD, 0, 0);
    transpose_split<<<gW, 256>>>(Wh, Whh, Whl, DD, DD, 0, 0);

    // --- Q/K projections (write hi/lo directly), V projection (fp32) ---
    dim3 gProj(DD / 256, NROWS / 128, 1);
    gemm_tc<true, false, true, false, false><<<gProj, 256, GEMM_SMEM>>>(
        xh, xl, Wqh, Wql, bq, nullptr, Qh, Ql, DD, DD, DD, DD, 1.0f, 0, 0, 0);
    gemm_tc<true, false, true, false, false><<<gProj, 256, GEMM_SMEM>>>(
        xh, xl, Wkh, Wkl, bk, nullptr, Kh, Kl, DD, DD, DD, DD, 1.0f, 0, 0, 0);
    gemm_tc<true, true, false, false, false><<<gProj, 256, GEMM_SMEM>>>(
        xh, xl, Wvh, Wvl, bv, Vp, nullptr, nullptr, DD, DD, DD, DD, 1.0f, 0, 0, 0);

    // --- V transpose+split: [T,D] -> [D,T] per batch ---
    dim3 gVt(DD / 32, TT / 32, BB);
    transpose_split<<<gVt, 256>>>(Vp, Vth, Vtl, TT, DD, (size_t)TT * DD, (size_t)TT * DD);

    // --- scores = (Q K^T) / 32, causal-skipped tiles ---
    dim3 gScore(TT / 256, TT / 128, BB);
    gemm_tc<false, true, false, true, false><<<gScore, 256, GEMM_SMEM>>>(
        Qh, Ql, Kh, Kl, nullptr, Sp, nullptr, nullptr, DD, DD, DD, TT, scale,
        (size_t)TT * DD, (size_t)TT * DD, (size_t)TT * TT);

    // --- softmax -> P hi/lo (zero-padded to 128 boundary) ---
    softmax_causal<<<NROWS, 256>>>(Sp, Ph, Pl);

    // --- O = P V (K truncated per row tile), write hi/lo ---
    dim3 gPV(DD / 256, TT / 128, BB);
    gemm_tc<false, false, true, false, true><<<gPV, 256, GEMM_SMEM>>>(
        Ph, Pl, Vth, Vtl, nullptr, nullptr, Oh, Ol, TT, TT, TT, DD, 1.0f,
        (size_t)TT * TT, (size_t)TT * DD, (size_t)TT * DD);

    // --- out = O Wh + bh ---
    gemm_tc<true, true, false, false, false><<<gProj, 256, GEMM_SMEM>>>(
        Oh, Ol, Whh, Whl, bh, out, nullptr, nullptr, DD, DD, DD, DD, 1.0f, 0, 0, 0);
}

// round 8
// speedup vs baseline: 4.7181x; 1.4660x over previous
#include <cuda_runtime.h>
#include <cuda_fp16.h>
#include <math.h>
#include <stdint.h>

typedef __half h16;

// Problem shape (fixed)
#define BB 4
#define TT 2048
#define DD 1024
#define NROWS (BB * TT)   // 8192

// ---------------------------------------------------------------------------
// Scratch (device globals — allocation is forbidden)
// ---------------------------------------------------------------------------
__device__ h16   g_x16[(size_t)NROWS * DD];            // x as fp16
__device__ h16   g_Wqkv[(size_t)3 * DD * DD];          // stacked Wq^T,Wk^T,Wv^T
__device__ float g_bqkv[3 * DD];                       // stacked biases
__device__ h16   g_Wht[(size_t)DD * DD];               // Wh^T
__device__ h16   g_Q[(size_t)NROWS * DD];
__device__ h16   g_K[(size_t)NROWS * DD];
__device__ h16   g_V[(size_t)NROWS * DD];
__device__ h16   g_Vt[(size_t)NROWS * DD];             // [B][D][T]
__device__ float g_S[(size_t)BB * TT * TT];
__device__ h16   g_P[(size_t)BB * TT * TT];
__device__ h16   g_O[(size_t)NROWS * DD];

// ---------------------------------------------------------------------------
// Low-level helpers (baseline PTX — valid at compute_103)
// ---------------------------------------------------------------------------
__device__ __forceinline__ uint32_t smem_u32(const void* p) {
    uint32_t a;
    asm("{ .reg .u64 t; cvta.to.shared.u64 t, %1; cvt.u32.u64 %0, t; }" : "=r"(a) : "l"(p));
    return a;
}

__device__ __forceinline__ void ldsm_x4(uint32_t* r, uint32_t addr) {
    asm volatile("ldmatrix.sync.aligned.m8n8.x4.shared.b16 {%0,%1,%2,%3}, [%4];"
                 : "=r"(r[0]), "=r"(r[1]), "=r"(r[2]), "=r"(r[3]) : "r"(addr));
}

__device__ __forceinline__ void mma16816h(float* c, const uint32_t* a, const uint32_t* b) {
    asm volatile(
        "mma.sync.aligned.m16n8k16.row.col.f32.f16.f16.f32 "
        "{%0,%1,%2,%3}, {%4,%5,%6,%7}, {%8,%9}, {%0,%1,%2,%3};"
        : "+f"(c[0]), "+f"(c[1]), "+f"(c[2]), "+f"(c[3])
        : "r"(a[0]), "r"(a[1]), "r"(a[2]), "r"(a[3]), "r"(b[0]), "r"(b[1]));
}

// ---------------------------------------------------------------------------
// fp16 tensor-core GEMM:  C[m,n] = sum_k A[m,k] * B[n,k]
// CTA tile 128x256, BK=32, 8 warps (2x4), warp tile 64x64, m16n8k16 MMA.
// 4-stage cp.async pipeline; one barrier per chunk.
// MODE: 0 = fp32 out (+scale,+bias opt), 1 = fp16 out, 2 = QKV region out.
// ---------------------------------------------------------------------------
#define ROW_B    80                     // 32 fp16 = 64B data, padded to 80B
#define A_TILE_B (128 * ROW_B)          // 10240 B
#define B_TILE_B (256 * ROW_B)          // 20480 B
#define STAGE_B  (A_TILE_B + B_TILE_B)  // 30720 B
#define STAGES   4
#define GEMM_SMEM (STAGES * STAGE_B)    // 122880 B

template <int ROWS>
__device__ __forceinline__ void load_tile_async(uint32_t sdst, const h16* __restrict__ g,
                                                int rowBase, int ld, int kBase, int tid) {
    #pragma unroll
    for (int p = 0; p < ROWS / 64; p++) {
        int c = tid + p * 256;
        int r = c >> 2;
        int ch = c & 3;                  // 16B chunk 0..3
        uint32_t dst = sdst + (uint32_t)(r * ROW_B + ch * 16);
        const char* src = (const char*)(g + (size_t)(rowBase + r) * ld + kBase) + ch * 16;
        asm volatile("cp.async.cg.shared.global [%0], [%1], 16;" :: "r"(dst), "l"(src));
    }
}

__device__ __forceinline__ void load_stage(uint32_t st, const h16* a, const h16* b,
                                           int mBase, int nBase, int ldA, int ldB,
                                           int kb, int tid) {
    load_tile_async<128>(st, a, mBase, ldA, kb, tid);
    load_tile_async<256>(st + A_TILE_B, b, nBase, ldB, kb, tid);
}

template <int MODE, bool BIAS, bool CAUSAL, bool TRUNC>
__global__ void __launch_bounds__(256) gemm_tc(
    const h16* __restrict__ A, const h16* __restrict__ B,
    const float* __restrict__ bias,
    float* __restrict__ C, h16* __restrict__ H,
    h16* __restrict__ Qd, h16* __restrict__ Kd, h16* __restrict__ Vd,
    int K, int ldA, int ldB, int ldC, float scale,
    size_t aBatch, size_t bBatch, size_t cBatch)
{
    extern __shared__ char smem[];
    const int nBase = blockIdx.x * 256;
    const int mBase = blockIdx.y * 128;
    if (CAUSAL && nBase >= mBase + 128) return;   // fully-masked tile

    const uint32_t sb = smem_u32(smem);
    const int tid = threadIdx.x;
    const int wid = tid >> 5;
    const int lane = tid & 31;
    const int wm = wid >> 2;        // 0..1 -> m offset wm*64
    const int wn = wid & 3;         // 0..3 -> n offset wn*64

    const h16* aB = A + (size_t)blockIdx.z * aBatch;
    const h16* bB = B + (size_t)blockIdx.z * bBatch;

    int kEnd = K;
    if (TRUNC) { int ke = mBase + 128; kEnd = ke < K ? ke : K; }
    const int nch = kEnd >> 5;      // BK = 32 (always >= 4 here)

    const uint32_t aOff = (uint32_t)((lane & 15) * ROW_B + (lane >> 4) * 16);
    const uint32_t bOff = (uint32_t)(((lane & 7) + 8 * (lane >> 4)) * ROW_B + ((lane >> 3) & 1) * 16);
    const uint32_t aWarp = (uint32_t)(wm * 64 * ROW_B) + aOff;
    const uint32_t bWarp = A_TILE_B + (uint32_t)(wn * 64 * ROW_B) + bOff;

    float acc[4][8][4];
    #pragma unroll
    for (int i = 0; i < 4; i++)
        #pragma unroll
        for (int j = 0; j < 8; j++)
            #pragma unroll
            for (int k = 0; k < 4; k++) acc[i][j][k] = 0.0f;

    // prologue: chunks 0..2 into stages 0..2
    #pragma unroll
    for (int s = 0; s < 3; s++) {
        load_stage(sb + (uint32_t)s * STAGE_B, aB, bB, mBase, nBase, ldA, ldB, s * 32, tid);
        asm volatile("cp.async.commit_group;" ::: "memory");
    }

    for (int c = 0; c < nch; c++) {
        asm volatile("cp.async.wait_group 2;" ::: "memory");
        __syncthreads();

        if (c + 3 < nch) {
            int sNext = (c + 3) & 3;
            load_stage(sb + (uint32_t)sNext * STAGE_B, aB, bB, mBase, nBase, ldA, ldB,
                       (c + 3) * 32, tid);
        }
        asm volatile("cp.async.commit_group;" ::: "memory");   // uniform group count

        const uint32_t st = sb + (uint32_t)(c & 3) * STAGE_B;
        const uint32_t aAddr = st + aWarp;
        const uint32_t bAddr = st + bWarp;

        #pragma unroll
        for (int ks = 0; ks < 2; ks++) {
            const uint32_t kb = (uint32_t)(ks * 32);   // 16 fp16 = 32 B
            uint32_t af[4][4];
            #pragma unroll
            for (int mf = 0; mf < 4; mf++)
                ldsm_x4(af[mf], aAddr + (uint32_t)(mf * 16 * ROW_B) + kb);
            uint32_t bf[8][2];
            #pragma unroll
            for (int np = 0; np < 4; np++) {
                uint32_t r4[4];
                ldsm_x4(r4, bAddr + (uint32_t)(np * 16 * ROW_B) + kb);
                bf[2 * np][0] = r4[0]; bf[2 * np][1] = r4[1];
                bf[2 * np + 1][0] = r4[2]; bf[2 * np + 1][1] = r4[3];
            }
            #pragma unroll
            for (int mf = 0; mf < 4; mf++)
                #pragma unroll
                for (int nf = 0; nf < 8; nf++)
                    mma16816h(acc[mf][nf], af[mf], bf[nf]);
        }
    }

    // epilogue
    const int gid = lane >> 2;      // 0..7
    const int tig = lane & 3;       // 0..3

    if (MODE == 2) {
        // QKV: column region selects destination (warp tile never straddles 1024)
        const int wcol = nBase + wn * 64;
        const int reg = wcol >> 10;                    // 0=Q 1=K 2=V
        h16* dst = (reg == 0) ? Qd : (reg == 1) ? Kd : Vd;
        #pragma unroll
        for (int mf = 0; mf < 4; mf++) {
            const int row0 = mBase + wm * 64 + mf * 16 + gid;
            #pragma unroll
            for (int nf = 0; nf < 8; nf++) {
                const int col0 = nBase + wn * 64 + nf * 8 + 2 * tig;
                float b0 = bias[col0];
                float b1 = bias[col0 + 1];
                const int nloc = col0 - (reg << 10);
                #pragma unroll
                for (int hh = 0; hh < 2; hh++) {
                    const int m = row0 + 8 * hh;
                    float v0 = acc[mf][nf][2 * hh + 0] + b0;
                    float v1 = acc[mf][nf][2 * hh + 1] + b1;
                    *(__half2*)&dst[(size_t)m * DD + nloc] = __floats2half2_rn(v0, v1);
                }
            }
        }
    } else {
        float* Cp = (MODE == 0) ? (C + (size_t)blockIdx.z * cBatch) : nullptr;
        h16*   Hp = (MODE == 1) ? (H + (size_t)blockIdx.z * cBatch) : nullptr;
        #pragma unroll
        for (int mf = 0; mf < 4; mf++) {
            const int row0 = mBase + wm * 64 + mf * 16 + gid;
            #pragma unroll
            for (int nf = 0; nf < 8; nf++) {
                const int col0 = nBase + wn * 64 + nf * 8 + 2 * tig;
                float b0 = BIAS ? bias[col0] : 0.0f;
                float b1 = BIAS ? bias[col0 + 1] : 0.0f;
                #pragma unroll
                for (int hh = 0; hh < 2; hh++) {
                    const int m = row0 + 8 * hh;
                    float v0 = acc[mf][nf][2 * hh + 0] * scale + b0;
                    float v1 = acc[mf][nf][2 * hh + 1] * scale + b1;
                    if (MODE == 0)
                        *(float2*)&Cp[(size_t)m * ldC + col0] = make_float2(v0, v1);
                    else
                        *(__half2*)&Hp[(size_t)m * ldC + col0] = __floats2half2_rn(v0, v1);
                }
            }
        }
    }
}

// ---------------------------------------------------------------------------
// Prep kernels
// ---------------------------------------------------------------------------
__global__ void __launch_bounds__(256) convert_h(const float* __restrict__ in,
                                                 h16* __restrict__ o, size_t n4)
{
    const float4* in4 = (const float4*)in;
    __half2* o2 = (__half2*)o;
    size_t i = (size_t)blockIdx.x * 256 + threadIdx.x;
    size_t stride = (size_t)gridDim.x * 256;
    for (; i < n4; i += stride) {
        float4 v = in4[i];
        o2[2 * i]     = __floats2half2_rn(v.x, v.y);
        o2[2 * i + 1] = __floats2half2_rn(v.z, v.w);
    }
}

__global__ void __launch_bounds__(256) bias_pack(const float* __restrict__ bq,
                                                 const float* __restrict__ bk,
                                                 const float* __restrict__ bv,
                                                 float* __restrict__ o)
{
    int i = blockIdx.x * 256 + threadIdx.x;
    if (i < DD) o[i] = bq[i];
    else if (i < 2 * DD) o[i] = bk[i - DD];
    else if (i < 3 * DD) o[i] = bv[i - 2 * DD];
}

// out[c][r] = (h16)in[r][c]  — fp32 weight transpose to fp16
__global__ void __launch_bounds__(256) transpose_wf(const float* __restrict__ in,
                                                    h16* __restrict__ o, int R, int C)
{
    __shared__ float t[32][33];
    const int x = blockIdx.x * 32;
    const int y = blockIdx.y * 32;
    const int tx = threadIdx.x & 31;
    const int ty = threadIdx.x >> 5;   // 0..7
    #pragma unroll
    for (int i = 0; i < 32; i += 8)
        t[ty + i][tx] = in[(size_t)(y + ty + i) * C + (x + tx)];
    __syncthreads();
    #pragma unroll
    for (int i = 0; i < 32; i += 8)
        o[(size_t)(x + ty + i) * R + (y + tx)] = __float2half(t[tx][ty + i]);
}

// out[c][r] = in[r][c]  fp16 -> fp16, per batch z (V transpose)
__global__ void __launch_bounds__(256) transpose_h(const h16* __restrict__ in,
                                                   h16* __restrict__ o,
                                                   int R, int C, size_t inB, size_t outB)
{
    __shared__ h16 t[32][33];
    const h16* ib = in + (size_t)blockIdx.z * inB;
    h16* ob = o + (size_t)blockIdx.z * outB;
    const int x = blockIdx.x * 32;
    const int y = blockIdx.y * 32;
    const int tx = threadIdx.x & 31;
    const int ty = threadIdx.x >> 5;
    #pragma unroll
    for (int i = 0; i < 32; i += 8)
        t[ty + i][tx] = ib[(size_t)(y + ty + i) * C + (x + tx)];
    __syncthreads();
    #pragma unroll
    for (int i = 0; i < 32; i += 8)
        ob[(size_t)(x + ty + i) * R + (y + tx)] = t[tx][ty + i];
}

// ---------------------------------------------------------------------------
// Causal softmax: S fp32 row -> P fp16, zero-padded to next 128-boundary.
// ---------------------------------------------------------------------------
__global__ void __launch_bounds__(256) softmax_causal(const float* __restrict__ S,
                                                      h16* __restrict__ P)
{
    const int r = blockIdx.x;
    const int b = r >> 11;
    const int t = r & (TT - 1);
    const size_t rowOff = (size_t)b * TT * TT + (size_t)t * TT;
    const float* p = S + rowOff;
    h16* ph = P + rowOff;
    const int n = t + 1;

    __shared__ float buf[TT];
    __shared__ float wred[8];
    const int tid = threadIdx.x;
    const int lane = tid & 31;
    const int wrp = tid >> 5;

    float m = -1e30f;
    const int nv = n >> 2;
    const float4* p4 = (const float4*)p;
    float4* b4 = (float4*)buf;
    for (int i = tid; i < nv; i += 256) {
        float4 v = p4[i];
        b4[i] = v;
        m = fmaxf(m, fmaxf(fmaxf(v.x, v.y), fmaxf(v.z, v.w)));
    }
    for (int i = nv * 4 + tid; i < n; i += 256) {
        float v = p[i]; buf[i] = v; m = fmaxf(m, v);
    }
    #pragma unroll
    for (int o = 16; o > 0; o >>= 1) m = fmaxf(m, __shfl_xor_sync(0xFFFFFFFFu, m, o));
    if (lane == 0) wred[wrp] = m;
    __syncthreads();
    float mAll = wred[0];
    #pragma unroll
    for (int w = 1; w < 8; w++) mAll = fmaxf(mAll, wred[w]);
    __syncthreads();

    float sum = 0.0f;
    for (int i = tid; i < nv; i += 256) {
        float4 v = b4[i];
        v.x = __expf(v.x - mAll); v.y = __expf(v.y - mAll);
        v.z = __expf(v.z - mAll); v.w = __expf(v.w - mAll);
        b4[i] = v;
        sum += v.x + v.y + v.z + v.w;
    }
    for (int i = nv * 4 + tid; i < n; i += 256) {
        float e = __expf(buf[i] - mAll); buf[i] = e; sum += e;
    }
    #pragma unroll
    for (int o = 16; o > 0; o >>= 1) sum += __shfl_xor_sync(0xFFFFFFFFu, sum, o);
    if (lane == 0) wred[wrp] = sum;
    __syncthreads();
    float sAll = wred[0];
    #pragma unroll
    for (int w = 1; w < 8; w++) sAll += wred[w];
    const float inv = 1.0f / sAll;

    const int n2 = n >> 1;
    __half2* ph2 = (__half2*)ph;
    for (int i = tid; i < n2; i += 256)
        ph2[i] = __floats2half2_rn(buf[2 * i] * inv, buf[2 * i + 1] * inv);
    if ((n & 1) && tid == 0)
        ph[n - 1] = __float2half(buf[n - 1] * inv);
    const int nPad = ((t >> 7) + 1) << 7;
    const h16 z = __float2half(0.0f);
    for (int i = n + tid; i < nPad; i += 256) ph[i] = z;
}

// ---------------------------------------------------------------------------
// Launch
// ---------------------------------------------------------------------------
extern "C" void kernel_launch(void* const* d_in, const int* in_sizes, int n_in,
                              void* d_out, int out_size)
{
    const float* x  = (const float*)d_in[0];
    const float* Wq = (const float*)d_in[1];
    const float* bq = (const float*)d_in[2];
    const float* Wk = (const float*)d_in[3];
    const float* bk = (const float*)d_in[4];
    const float* Wv = (const float*)d_in[5];
    const float* bv = (const float*)d_in[6];
    const float* Wh = (const float*)d_in[7];
    const float* bh = (const float*)d_in[8];
    float* out = (float*)d_out;

    h16 *x16, *Wqkv, *Wht, *Qp, *Kp, *Vp, *Vt, *Pp, *Op;
    float *bqkv, *Sp;
    cudaGetSymbolAddress((void**)&x16, g_x16);
    cudaGetSymbolAddress((void**)&Wqkv, g_Wqkv);
    cudaGetSymbolAddress((void**)&bqkv, g_bqkv);
    cudaGetSymbolAddress((void**)&Wht, g_Wht);
    cudaGetSymbolAddress((void**)&Qp, g_Q);
    cudaGetSymbolAddress((void**)&Kp, g_K);
    cudaGetSymbolAddress((void**)&Vp, g_V);
    cudaGetSymbolAddress((void**)&Vt, g_Vt);
    cudaGetSymbolAddress((void**)&Sp, g_S);
    cudaGetSymbolAddress((void**)&Pp, g_P);
    cudaGetSymbolAddress((void**)&Op, g_O);

    cudaFuncSetAttribute(gemm_tc<2, true,  false, false>, cudaFuncAttributeMaxDynamicSharedMemorySize, GEMM_SMEM);
    cudaFuncSetAttribute(gemm_tc<0, false, true,  false>, cudaFuncAttributeMaxDynamicSharedMemorySize, GEMM_SMEM);
    cudaFuncSetAttribute(gemm_tc<1, false, false, true >, cudaFuncAttributeMaxDynamicSharedMemorySize, GEMM_SMEM);
    cudaFuncSetAttribute(gemm_tc<0, true,  false, false>, cudaFuncAttributeMaxDynamicSharedMemorySize, GEMM_SMEM);

    const float scale = 1.0f / 32.0f;   // 1/sqrt(1024)

    // --- prep ---
    convert_h<<<512, 256>>>(x, x16, (size_t)NROWS * DD / 4);
    bias_pack<<<12, 256>>>(bq, bk, bv, bqkv);
    dim3 gW(DD / 32, DD / 32, 1);
    transpose_wf<<<gW, 256>>>(Wq, Wqkv,                       DD, DD);
    transpose_wf<<<gW, 256>>>(Wk, Wqkv + (size_t)DD * DD,     DD, DD);
    transpose_wf<<<gW, 256>>>(Wv, Wqkv + (size_t)2 * DD * DD, DD, DD);
    transpose_wf<<<gW, 256>>>(Wh, Wht,                        DD, DD);

    // --- fused QKV projection: [8192,1024] @ [1024,3072] + bias ---
    dim3 gQKV(3 * DD / 256, NROWS / 128, 1);
    gemm_tc<2, true, false, false><<<gQKV, 256, GEMM_SMEM>>>(
        x16, Wqkv, bqkv, nullptr, nullptr, Qp, Kp, Vp,
        DD, DD, DD, 0, 1.0f, 0, 0, 0);

    // --- V transpose: [T,D] -> [D,T] per batch ---
    dim3 gVt(DD / 32, TT / 32, BB);
    transpose_h<<<gVt, 256>>>(Vp, Vt, TT, DD, (size_t)TT * DD, (size_t)TT * DD);

    // --- scores = (Q K^T)/32, causal-skipped tiles ---
    dim3 gScore(TT / 256, TT / 128, BB);
    gemm_tc<0, false, true, false><<<gScore, 256, GEMM_SMEM>>>(
        Qp, Kp, nullptr, Sp, nullptr, nullptr, nullptr, nullptr,
        DD, DD, DD, TT, scale,
        (size_t)TT * DD, (size_t)TT * DD, (size_t)TT * TT);

    // --- softmax -> P fp16 (zero-padded to 128 boundary) ---
    softmax_causal<<<NROWS, 256>>>(Sp, Pp);

    // --- O = P V (K truncated per row tile) ---
    dim3 gPV(DD / 256, TT / 128, BB);
    gemm_tc<1, false, false, true><<<gPV, 256, GEMM_SMEM>>>(
        Pp, Vt, nullptr, nullptr, Op, nullptr, nullptr, nullptr,
        TT, TT, TT, DD, 1.0f,
        (size_t)TT * TT, (size_t)TT * DD, (size_t)TT * DD);

    // --- out = O Wh + bh ---
    dim3 gOut(DD / 256, NROWS / 128, 1);
    gemm_tc<0, true, false, false><<<gOut, 256, GEMM_SMEM>>>(
        Op, Wht, bh, out, nullptr, nullptr, nullptr, nullptr,
        DD, DD, DD, DD, 1.0f, 0, 0, 0);
}

// round 9
// speedup vs baseline: 7.3765x; 1.5634x over previous
#include <cuda_runtime.h>
#include <cuda_fp16.h>
#include <math.h>
#include <stdint.h>

typedef __half h16;

// Problem shape (fixed)
#define BB 4
#define TT 2048
#define DD 1024
#define NROWS (BB * TT)   // 8192

// ---------------------------------------------------------------------------
// Scratch (device globals — allocation is forbidden)
// ---------------------------------------------------------------------------
__device__ h16   g_x16[(size_t)NROWS * DD];            // x as fp16
__device__ h16   g_Wqkv[(size_t)3 * DD * DD];          // stacked Wq^T,Wk^T,Wv^T
__device__ float g_bqkv[3 * DD];                       // stacked biases
__device__ h16   g_Wht[(size_t)DD * DD];               // Wh^T
__device__ h16   g_Q[(size_t)NROWS * DD];
__device__ h16   g_K[(size_t)NROWS * DD];
__device__ h16   g_V[(size_t)NROWS * DD];
__device__ float g_S[(size_t)BB * TT * TT];
__device__ h16   g_P[(size_t)BB * TT * TT];
__device__ h16   g_O[(size_t)NROWS * DD];

// ---------------------------------------------------------------------------
// Low-level helpers (baseline PTX — valid at compute_103)
// ---------------------------------------------------------------------------
__device__ __forceinline__ uint32_t smem_u32(const void* p) {
    uint32_t a;
    asm("{ .reg .u64 t; cvta.to.shared.u64 t, %1; cvt.u32.u64 %0, t; }" : "=r"(a) : "l"(p));
    return a;
}

__device__ __forceinline__ void ldsm_x4(uint32_t* r, uint32_t addr) {
    asm volatile("ldmatrix.sync.aligned.m8n8.x4.shared.b16 {%0,%1,%2,%3}, [%4];"
                 : "=r"(r[0]), "=r"(r[1]), "=r"(r[2]), "=r"(r[3]) : "r"(addr));
}

__device__ __forceinline__ void ldsm_x4_t(uint32_t* r, uint32_t addr) {
    asm volatile("ldmatrix.sync.aligned.m8n8.x4.trans.shared.b16 {%0,%1,%2,%3}, [%4];"
                 : "=r"(r[0]), "=r"(r[1]), "=r"(r[2]), "=r"(r[3]) : "r"(addr));
}

__device__ __forceinline__ void mma16816h(float* c, const uint32_t* a, const uint32_t* b) {
    asm volatile(
        "mma.sync.aligned.m16n8k16.row.col.f32.f16.f16.f32 "
        "{%0,%1,%2,%3}, {%4,%5,%6,%7}, {%8,%9}, {%0,%1,%2,%3};"
        : "+f"(c[0]), "+f"(c[1]), "+f"(c[2]), "+f"(c[3])
        : "r"(a[0]), "r"(a[1]), "r"(a[2]), "r"(a[3]), "r"(b[0]), "r"(b[1]));
}

// ---------------------------------------------------------------------------
// fp16 tensor-core GEMM:  C[m,n] = sum_k A[m,k] * B[n,k]
// CTA tile 128x256, BK=32, 8 warps (2x4), warp tile 64x64, m16n8k16 MMA.
// 4-stage cp.async pipeline; one barrier per chunk.
// MODE: 0 = fp32 out, 1 = fp16 out, 2 = QKV region out.
// BTRANS: B given row-major [K][N] (e.g. V [T,D]); loaded via ldmatrix.trans.
// ---------------------------------------------------------------------------
#define ROW_B    80                     // 32 fp16 = 64B data, padded to 80B
#define A_TILE_B (128 * ROW_B)          // 10240 B
#define B_TILE_B (256 * ROW_B)          // 20480 B (K-major B)
#define BTROW_B  528                    // 256 fp16 = 512B data, padded to 528B
#define BT_TILE_B (32 * BTROW_B)        // 16896 B (row-major B)
#define STAGES   4
#define GEMM_SMEM_N (STAGES * (A_TILE_B + B_TILE_B))    // 122880
#define GEMM_SMEM_T (STAGES * (A_TILE_B + BT_TILE_B))   // 108544

template <int ROWS>
__device__ __forceinline__ void load_tile_async(uint32_t sdst, const h16* __restrict__ g,
                                                int rowBase, int ld, int kBase, int tid) {
    #pragma unroll
    for (int p = 0; p < ROWS / 64; p++) {
        int c = tid + p * 256;
        int r = c >> 2;
        int ch = c & 3;                  // 16B chunk 0..3
        uint32_t dst = sdst + (uint32_t)(r * ROW_B + ch * 16);
        const char* src = (const char*)(g + (size_t)(rowBase + r) * ld + kBase) + ch * 16;
        asm volatile("cp.async.cg.shared.global [%0], [%1], 16;" :: "r"(dst), "l"(src));
    }
}

// row-major B tile: 32 k-rows x 512B of n
__device__ __forceinline__ void load_btile_trans(uint32_t sdst, const h16* __restrict__ g,
                                                 int kBase, int nBase, int ld, int tid) {
    #pragma unroll
    for (int p = 0; p < 4; p++) {
        int c = tid + p * 256;           // 0..1023
        int r = c >> 5;                  // k-row 0..31
        int cb = (c & 31) * 16;          // byte col 0..496
        uint32_t dst = sdst + (uint32_t)(r * BTROW_B + cb);
        const char* src = (const char*)(g + (size_t)(kBase + r) * ld + nBase) + cb;
        asm volatile("cp.async.cg.shared.global [%0], [%1], 16;" :: "r"(dst), "l"(src));
    }
}

template <bool BTRANS>
__device__ __forceinline__ void load_stage(uint32_t st, const h16* a, const h16* b,
                                           int mBase, int nBase, int ldA, int ldB,
                                           int kb, int tid) {
    load_tile_async<128>(st, a, mBase, ldA, kb, tid);
    if (BTRANS) load_btile_trans(st + A_TILE_B, b, kb, nBase, ldB, tid);
    else        load_tile_async<256>(st + A_TILE_B, b, nBase, ldB, kb, tid);
}

template <int MODE, bool BIAS, bool CAUSAL, bool TRUNC, bool BTRANS>
__global__ void __launch_bounds__(256) gemm_tc(
    const h16* __restrict__ A, const h16* __restrict__ B,
    const float* __restrict__ bias,
    float* __restrict__ C, h16* __restrict__ H,
    h16* __restrict__ Qd, h16* __restrict__ Kd, h16* __restrict__ Vd,
    int K, int ldA, int ldB, int ldC, float scale,
    size_t aBatch, size_t bBatch, size_t cBatch)
{
    extern __shared__ char smem[];
    constexpr uint32_t STG = A_TILE_B + (BTRANS ? BT_TILE_B : B_TILE_B);
    const int nBase = blockIdx.x * 256;
    const int mBase = blockIdx.y * 128;
    if (CAUSAL && nBase >= mBase + 128) return;   // fully-masked tile

    const uint32_t sb = smem_u32(smem);
    const int tid = threadIdx.x;
    const int wid = tid >> 5;
    const int lane = tid & 31;
    const int wm = wid >> 2;        // 0..1 -> m offset wm*64
    const int wn = wid & 3;         // 0..3 -> n offset wn*64

    const h16* aB = A + (size_t)blockIdx.z * aBatch;
    const h16* bB = B + (size_t)blockIdx.z * bBatch;

    int kEnd = K;
    if (TRUNC) { int ke = mBase + 128; kEnd = ke < K ? ke : K; }
    const int nch = kEnd >> 5;      // BK = 32 (always >= 4 here)

    const uint32_t aOff = (uint32_t)((lane & 15) * ROW_B + (lane >> 4) * 16);
    const uint32_t aWarp = (uint32_t)(wm * 64 * ROW_B) + aOff;
    // K-major B (non-trans): row = n, 16B chunk along k
    const uint32_t bOffN = (uint32_t)(((lane & 7) + 8 * (lane >> 4)) * ROW_B + ((lane >> 3) & 1) * 16);
    const uint32_t bWarpN = A_TILE_B + (uint32_t)(wn * 64 * ROW_B) + bOffN;
    // row-major B (trans): row = k, 16B chunk along n
    const uint32_t bOffT = (uint32_t)(((lane & 7) + 8 * ((lane >> 3) & 1)) * BTROW_B + (lane >> 4) * 16);
    const uint32_t bWarpT = A_TILE_B + (uint32_t)(wn * 64 * 2) + bOffT;

    float acc[4][8][4];
    #pragma unroll
    for (int i = 0; i < 4; i++)
        #pragma unroll
        for (int j = 0; j < 8; j++)
            #pragma unroll
            for (int k = 0; k < 4; k++) acc[i][j][k] = 0.0f;

    // prologue: chunks 0..2 into stages 0..2
    #pragma unroll
    for (int s = 0; s < 3; s++) {
        load_stage<BTRANS>(sb + (uint32_t)s * STG, aB, bB, mBase, nBase, ldA, ldB, s * 32, tid);
        asm volatile("cp.async.commit_group;" ::: "memory");
    }

    for (int c = 0; c < nch; c++) {
        asm volatile("cp.async.wait_group 2;" ::: "memory");
        __syncthreads();

        if (c + 3 < nch) {
            int sNext = (c + 3) & 3;
            load_stage<BTRANS>(sb + (uint32_t)sNext * STG, aB, bB, mBase, nBase, ldA, ldB,
                               (c + 3) * 32, tid);
        }
        asm volatile("cp.async.commit_group;" ::: "memory");   // uniform group count

        const uint32_t st = sb + (uint32_t)(c & 3) * STG;
        const uint32_t aAddr = st + aWarp;

        #pragma unroll
        for (int ks = 0; ks < 2; ks++) {
            uint32_t af[4][4];
            #pragma unroll
            for (int mf = 0; mf < 4; mf++)
                ldsm_x4(af[mf], aAddr + (uint32_t)(mf * 16 * ROW_B + ks * 32));
            uint32_t bf[8][2];
            if (BTRANS) {
                const uint32_t bAddr = st + bWarpT + (uint32_t)(ks * 16 * BTROW_B);
                #pragma unroll
                for (int np = 0; np < 4; np++) {
                    uint32_t r4[4];
                    ldsm_x4_t(r4, bAddr + (uint32_t)(np * 32));
                    bf[2 * np][0] = r4[0]; bf[2 * np][1] = r4[1];
                    bf[2 * np + 1][0] = r4[2]; bf[2 * np + 1][1] = r4[3];
                }
            } else {
                const uint32_t bAddr = st + bWarpN + (uint32_t)(ks * 32);
                #pragma unroll
                for (int np = 0; np < 4; np++) {
                    uint32_t r4[4];
                    ldsm_x4(r4, bAddr + (uint32_t)(np * 16 * ROW_B));
                    bf[2 * np][0] = r4[0]; bf[2 * np][1] = r4[1];
                    bf[2 * np + 1][0] = r4[2]; bf[2 * np + 1][1] = r4[3];
                }
            }
            #pragma unroll
            for (int mf = 0; mf < 4; mf++)
                #pragma unroll
                for (int nf = 0; nf < 8; nf++)
                    mma16816h(acc[mf][nf], af[mf], bf[nf]);
        }
    }

    // epilogue
    const int gid = lane >> 2;      // 0..7
    const int tig = lane & 3;       // 0..3

    if (MODE == 2) {
        // QKV: column region selects destination (warp tile never straddles 1024)
        const int wcol = nBase + wn * 64;
        const int reg = wcol >> 10;                    // 0=Q 1=K 2=V
        h16* dst = (reg == 0) ? Qd : (reg == 1) ? Kd : Vd;
        #pragma unroll
        for (int mf = 0; mf < 4; mf++) {
            const int row0 = mBase + wm * 64 + mf * 16 + gid;
            #pragma unroll
            for (int nf = 0; nf < 8; nf++) {
                const int col0 = nBase + wn * 64 + nf * 8 + 2 * tig;
                float b0 = bias[col0];
                float b1 = bias[col0 + 1];
                const int nloc = col0 - (reg << 10);
                #pragma unroll
                for (int hh = 0; hh < 2; hh++) {
                    const int m = row0 + 8 * hh;
                    float v0 = acc[mf][nf][2 * hh + 0] + b0;
                    float v1 = acc[mf][nf][2 * hh + 1] + b1;
                    *(__half2*)&dst[(size_t)m * DD + nloc] = __floats2half2_rn(v0, v1);
                }
            }
        }
    } else {
        float* Cp = (MODE == 0) ? (C + (size_t)blockIdx.z * cBatch) : nullptr;
        h16*   Hp = (MODE == 1) ? (H + (size_t)blockIdx.z * cBatch) : nullptr;
        #pragma unroll
        for (int mf = 0; mf < 4; mf++) {
            const int row0 = mBase + wm * 64 + mf * 16 + gid;
            #pragma unroll
            for (int nf = 0; nf < 8; nf++) {
                const int col0 = nBase + wn * 64 + nf * 8 + 2 * tig;
                float b0 = BIAS ? bias[col0] : 0.0f;
                float b1 = BIAS ? bias[col0 + 1] : 0.0f;
                #pragma unroll
                for (int hh = 0; hh < 2; hh++) {
                    const int m = row0 + 8 * hh;
                    float v0 = acc[mf][nf][2 * hh + 0] * scale + b0;
                    float v1 = acc[mf][nf][2 * hh + 1] * scale + b1;
                    if (MODE == 0)
                        *(float2*)&Cp[(size_t)m * ldC + col0] = make_float2(v0, v1);
                    else
                        *(__half2*)&Hp[(size_t)m * ldC + col0] = __floats2half2_rn(v0, v1);
                }
            }
        }
    }
}

// ---------------------------------------------------------------------------
// Prep kernels
// ---------------------------------------------------------------------------
__global__ void __launch_bounds__(256) convert_h(const float* __restrict__ in,
                                                 h16* __restrict__ o, size_t n4)
{
    const float4* in4 = (const float4*)in;
    __half2* o2 = (__half2*)o;
    size_t i = (size_t)blockIdx.x * 256 + threadIdx.x;
    size_t stride = (size_t)gridDim.x * 256;
    for (; i < n4; i += stride) {
        float4 v = in4[i];
        o2[2 * i]     = __floats2half2_rn(v.x, v.y);
        o2[2 * i + 1] = __floats2half2_rn(v.z, v.w);
    }
}

__global__ void __launch_bounds__(256) bias_pack(const float* __restrict__ bq,
                                                 const float* __restrict__ bk,
                                                 const float* __restrict__ bv,
                                                 float* __restrict__ o)
{
    int i = blockIdx.x * 256 + threadIdx.x;
    if (i < DD) o[i] = bq[i];
    else if (i < 2 * DD) o[i] = bk[i - DD];
    else if (i < 3 * DD) o[i] = bv[i - 2 * DD];
}

// Fused: out_z[c][r] = (h16)in_z[r][c] for the 4 weight matrices (z selects)
__global__ void __launch_bounds__(256) transpose_wf4(
    const float* __restrict__ w0, const float* __restrict__ w1,
    const float* __restrict__ w2, const float* __restrict__ w3,
    h16* __restrict__ o0, h16* __restrict__ o1,
    h16* __restrict__ o2, h16* __restrict__ o3)
{
    __shared__ float t[32][33];
    const int z = blockIdx.z;
    const float* in = (z == 0) ? w0 : (z == 1) ? w1 : (z == 2) ? w2 : w3;
    h16* o = (z == 0) ? o0 : (z == 1) ? o1 : (z == 2) ? o2 : o3;
    const int x = blockIdx.x * 32;
    const int y = blockIdx.y * 32;
    const int tx = threadIdx.x & 31;
    const int ty = threadIdx.x >> 5;   // 0..7
    #pragma unroll
    for (int i = 0; i < 32; i += 8)
        t[ty + i][tx] = in[(size_t)(y + ty + i) * DD + (x + tx)];
    __syncthreads();
    #pragma unroll
    for (int i = 0; i < 32; i += 8)
        o[(size_t)(x + ty + i) * DD + (y + tx)] = __float2half(t[tx][ty + i]);
}

// ---------------------------------------------------------------------------
// Causal softmax: S fp32 row -> P fp16, zero-padded to next 128-boundary.
// ---------------------------------------------------------------------------
__global__ void __launch_bounds__(256) softmax_causal(const float* __restrict__ S,
                                                      h16* __restrict__ P)
{
    const int r = blockIdx.x;
    const int b = r >> 11;
    const int t = r & (TT - 1);
    const size_t rowOff = (size_t)b * TT * TT + (size_t)t * TT;
    const float* p = S + rowOff;
    h16* ph = P + rowOff;
    const int n = t + 1;

    __shared__ float buf[TT];
    __shared__ float wred[8];
    const int tid = threadIdx.x;
    const int lane = tid & 31;
    const int wrp = tid >> 5;

    float m = -1e30f;
    const int nv = n >> 2;
    const float4* p4 = (const float4*)p;
    float4* b4 = (float4*)buf;
    for (int i = tid; i < nv; i += 256) {
        float4 v = p4[i];
        b4[i] = v;
        m = fmaxf(m, fmaxf(fmaxf(v.x, v.y), fmaxf(v.z, v.w)));
    }
    for (int i = nv * 4 + tid; i < n; i += 256) {
        float v = p[i]; buf[i] = v; m = fmaxf(m, v);
    }
    #pragma unroll
    for (int o = 16; o > 0; o >>= 1) m = fmaxf(m, __shfl_xor_sync(0xFFFFFFFFu, m, o));
    if (lane == 0) wred[wrp] = m;
    __syncthreads();
    float mAll = wred[0];
    #pragma unroll
    for (int w = 1; w < 8; w++) mAll = fmaxf(mAll, wred[w]);
    __syncthreads();

    float sum = 0.0f;
    for (int i = tid; i < nv; i += 256) {
        float4 v = b4[i];
        v.x = __expf(v.x - mAll); v.y = __expf(v.y - mAll);
        v.z = __expf(v.z - mAll); v.w = __expf(v.w - mAll);
        b4[i] = v;
        sum += v.x + v.y + v.z + v.w;
    }
    for (int i = nv * 4 + tid; i < n; i += 256) {
        float e = __expf(buf[i] - mAll); buf[i] = e; sum += e;
    }
    #pragma unroll
    for (int o = 16; o > 0; o >>= 1) sum += __shfl_xor_sync(0xFFFFFFFFu, sum, o);
    if (lane == 0) wred[wrp] = sum;
    __syncthreads();
    float sAll = wred[0];
    #pragma unroll
    for (int w = 1; w < 8; w++) sAll += wred[w];
    const float inv = 1.0f / sAll;

    const int n2 = n >> 1;
    __half2* ph2 = (__half2*)ph;
    for (int i = tid; i < n2; i += 256)
        ph2[i] = __floats2half2_rn(buf[2 * i] * inv, buf[2 * i + 1] * inv);
    if ((n & 1) && tid == 0)
        ph[n - 1] = __float2half(buf[n - 1] * inv);
    const int nPad = ((t >> 7) + 1) << 7;
    const h16 z = __float2half(0.0f);
    for (int i = n + tid; i < nPad; i += 256) ph[i] = z;
}

// ---------------------------------------------------------------------------
// Launch
// ---------------------------------------------------------------------------
extern "C" void kernel_launch(void* const* d_in, const int* in_sizes, int n_in,
                              void* d_out, int out_size)
{
    const float* x  = (const float*)d_in[0];
    const float* Wq = (const float*)d_in[1];
    const float* bq = (const float*)d_in[2];
    const float* Wk = (const float*)d_in[3];
    const float* bk = (const float*)d_in[4];
    const float* Wv = (const float*)d_in[5];
    const float* bv = (const float*)d_in[6];
    const float* Wh = (const float*)d_in[7];
    const float* bh = (const float*)d_in[8];
    float* out = (float*)d_out;

    h16 *x16, *Wqkv, *Wht, *Qp, *Kp, *Vp, *Pp, *Op;
    float *bqkv, *Sp;
    cudaGetSymbolAddress((void**)&x16, g_x16);
    cudaGetSymbolAddress((void**)&Wqkv, g_Wqkv);
    cudaGetSymbolAddress((void**)&bqkv, g_bqkv);
    cudaGetSymbolAddress((void**)&Wht, g_Wht);
    cudaGetSymbolAddress((void**)&Qp, g_Q);
    cudaGetSymbolAddress((void**)&Kp, g_K);
    cudaGetSymbolAddress((void**)&Vp, g_V);
    cudaGetSymbolAddress((void**)&Sp, g_S);
    cudaGetSymbolAddress((void**)&Pp, g_P);
    cudaGetSymbolAddress((void**)&Op, g_O);

    cudaFuncSetAttribute(gemm_tc<2, true,  false, false, false>, cudaFuncAttributeMaxDynamicSharedMemorySize, GEMM_SMEM_N);
    cudaFuncSetAttribute(gemm_tc<0, false, true,  false, false>, cudaFuncAttributeMaxDynamicSharedMemorySize, GEMM_SMEM_N);
    cudaFuncSetAttribute(gemm_tc<1, false, false, true,  true >, cudaFuncAttributeMaxDynamicSharedMemorySize, GEMM_SMEM_T);
    cudaFuncSetAttribute(gemm_tc<0, true,  false, false, false>, cudaFuncAttributeMaxDynamicSharedMemorySize, GEMM_SMEM_N);

    const float scale = 1.0f / 32.0f;   // 1/sqrt(1024)

    // --- prep ---
    convert_h<<<512, 256>>>(x, x16, (size_t)NROWS * DD / 4);
    bias_pack<<<12, 256>>>(bq, bk, bv, bqkv);
    dim3 gW(DD / 32, DD / 32, 4);
    transpose_wf4<<<gW, 256>>>(Wq, Wk, Wv, Wh,
                               Wqkv, Wqkv + (size_t)DD * DD, Wqkv + (size_t)2 * DD * DD, Wht);

    // --- fused QKV projection: [8192,1024] @ [1024,3072] + bias ---
    dim3 gQKV(3 * DD / 256, NROWS / 128, 1);
    gemm_tc<2, true, false, false, false><<<gQKV, 256, GEMM_SMEM_N>>>(
        x16, Wqkv, bqkv, nullptr, nullptr, Qp, Kp, Vp,
        DD, DD, DD, 0, 1.0f, 0, 0, 0);

    // --- scores = (Q K^T)/32, causal-skipped tiles ---
    dim3 gScore(TT / 256, TT / 128, BB);
    gemm_tc<0, false, true, false, false><<<gScore, 256, GEMM_SMEM_N>>>(
        Qp, Kp, nullptr, Sp, nullptr, nullptr, nullptr, nullptr,
        DD, DD, DD, TT, scale,
        (size_t)TT * DD, (size_t)TT * DD, (size_t)TT * TT);

    // --- softmax -> P fp16 (zero-padded to 128 boundary) ---
    softmax_causal<<<NROWS, 256>>>(Sp, Pp);

    // --- O = P V (K truncated per row tile), V consumed row-major via trans ---
    dim3 gPV(DD / 256, TT / 128, BB);
    gemm_tc<1, false, false, true, true><<<gPV, 256, GEMM_SMEM_T>>>(
        Pp, Vp, nullptr, nullptr, Op, nullptr, nullptr, nullptr,
        TT, TT, DD, DD, 1.0f,
        (size_t)TT * TT, (size_t)TT * DD, (size_t)TT * DD);

    // --- out = O Wh + bh ---
    dim3 gOut(DD / 256, NROWS / 128, 1);
    gemm_tc<0, true, false, false, false><<<gOut, 256, GEMM_SMEM_N>>>(
        Op, Wht, bh, out, nullptr, nullptr, nullptr, nullptr,
        DD, DD, DD, DD, 1.0f, 0, 0, 0);
}

// round 10
// speedup vs baseline: 9.5449x; 1.2940x over previous
#include <cuda_runtime.h>
#include <cuda_fp16.h>
#include <math.h>
#include <stdint.h>

typedef __half h16;

// Problem shape (fixed)
#define BB 4
#define TT 2048
#define DD 1024
#define NROWS (BB * TT)   // 8192

// ---------------------------------------------------------------------------
// Scratch (device globals — allocation is forbidden)
// ---------------------------------------------------------------------------
__device__ h16   g_x16[(size_t)NROWS * DD];            // x as fp16
__device__ h16   g_Wqkv[(size_t)3 * DD * DD];          // stacked Wq^T,Wk^T,Wv^T
__device__ float g_bqkv[3 * DD];                       // stacked biases
__device__ h16   g_Wht[(size_t)DD * DD];               // Wh^T
__device__ h16   g_Q[(size_t)NROWS * DD];
__device__ h16   g_K[(size_t)NROWS * DD];
__device__ h16   g_V[(size_t)NROWS * DD];
__device__ float g_S[(size_t)BB * TT * TT];
__device__ h16   g_P[(size_t)BB * TT * TT];
__device__ h16   g_O[(size_t)NROWS * DD];

// ---------------------------------------------------------------------------
// Low-level helpers (baseline PTX — valid at compute_103)
// ---------------------------------------------------------------------------
__device__ __forceinline__ uint32_t smem_u32(const void* p) {
    uint32_t a;
    asm("{ .reg .u64 t; cvta.to.shared.u64 t, %1; cvt.u32.u64 %0, t; }" : "=r"(a) : "l"(p));
    return a;
}

__device__ __forceinline__ void ldsm_x4(uint32_t* r, uint32_t addr) {
    asm volatile("ldmatrix.sync.aligned.m8n8.x4.shared.b16 {%0,%1,%2,%3}, [%4];"
                 : "=r"(r[0]), "=r"(r[1]), "=r"(r[2]), "=r"(r[3]) : "r"(addr));
}

__device__ __forceinline__ void ldsm_x4_t(uint32_t* r, uint32_t addr) {
    asm volatile("ldmatrix.sync.aligned.m8n8.x4.trans.shared.b16 {%0,%1,%2,%3}, [%4];"
                 : "=r"(r[0]), "=r"(r[1]), "=r"(r[2]), "=r"(r[3]) : "r"(addr));
}

__device__ __forceinline__ void mma16816h(float* c, const uint32_t* a, const uint32_t* b) {
    asm volatile(
        "mma.sync.aligned.m16n8k16.row.col.f32.f16.f16.f32 "
        "{%0,%1,%2,%3}, {%4,%5,%6,%7}, {%8,%9}, {%0,%1,%2,%3};"
        : "+f"(c[0]), "+f"(c[1]), "+f"(c[2]), "+f"(c[3])
        : "r"(a[0]), "r"(a[1]), "r"(a[2]), "r"(a[3]), "r"(b[0]), "r"(b[1]));
}

// ---------------------------------------------------------------------------
// fp16 tensor-core GEMM:  C[m,n] = sum_k A[m,k] * B[n,k]
// CTA tile 128x128, BK=32, 4 warps (2x2), warp tile 64x64, m16n8k16 MMA.
// 128 threads/CTA, 80KB smem -> 2 CTAs/SM for latency hiding.
// MODE: 0 = fp32 out, 1 = fp16 out, 2 = QKV region out.
// BTRANS: B given row-major [K][N] (e.g. V [T,D]); loaded via ldmatrix.trans.
// ---------------------------------------------------------------------------
#define NTHR     128
#define ROW_B    80                     // 32 fp16 = 64B data, padded to 80B
#define A_TILE_B (128 * ROW_B)          // 10240 B
#define B_TILE_B (128 * ROW_B)          // 10240 B (K-major B, 128 n-rows)
#define BTROW_B  272                    // 128 fp16 = 256B data, padded to 272B
#define BT_TILE_B (32 * BTROW_B)        // 8704 B (row-major B)
#define STAGES   4
#define GEMM_SMEM_N (STAGES * (A_TILE_B + B_TILE_B))    // 81920
#define GEMM_SMEM_T (STAGES * (A_TILE_B + BT_TILE_B))   // 75776

// ROWS rows x 64B (4x16B chunks per row), 128 threads
template <int ROWS>
__device__ __forceinline__ void load_tile_async(uint32_t sdst, const h16* __restrict__ g,
                                                int rowBase, int ld, int kBase, int tid) {
    #pragma unroll
    for (int p = 0; p < ROWS / 32; p++) {
        int c = tid + p * NTHR;
        int r = c >> 2;
        int ch = c & 3;                  // 16B chunk 0..3
        uint32_t dst = sdst + (uint32_t)(r * ROW_B + ch * 16);
        const char* src = (const char*)(g + (size_t)(rowBase + r) * ld + kBase) + ch * 16;
        asm volatile("cp.async.cg.shared.global [%0], [%1], 16;" :: "r"(dst), "l"(src));
    }
}

// row-major B tile: 32 k-rows x 256B of n (16 x 16B chunks per row)
__device__ __forceinline__ void load_btile_trans(uint32_t sdst, const h16* __restrict__ g,
                                                 int kBase, int nBase, int ld, int tid) {
    #pragma unroll
    for (int p = 0; p < 4; p++) {
        int c = tid + p * NTHR;          // 0..511
        int r = c >> 4;                  // k-row 0..31
        int cb = (c & 15) * 16;          // byte col 0..240
        uint32_t dst = sdst + (uint32_t)(r * BTROW_B + cb);
        const char* src = (const char*)(g + (size_t)(kBase + r) * ld + nBase) + cb;
        asm volatile("cp.async.cg.shared.global [%0], [%1], 16;" :: "r"(dst), "l"(src));
    }
}

template <bool BTRANS>
__device__ __forceinline__ void load_stage(uint32_t st, const h16* a, const h16* b,
                                           int mBase, int nBase, int ldA, int ldB,
                                           int kb, int tid) {
    load_tile_async<128>(st, a, mBase, ldA, kb, tid);
    if (BTRANS) load_btile_trans(st + A_TILE_B, b, kb, nBase, ldB, tid);
    else        load_tile_async<128>(st + A_TILE_B, b, nBase, ldB, kb, tid);
}

template <int MODE, bool BIAS, bool CAUSAL, bool TRUNC, bool BTRANS>
__global__ void __launch_bounds__(NTHR) gemm_tc(
    const h16* __restrict__ A, const h16* __restrict__ B,
    const float* __restrict__ bias,
    float* __restrict__ C, h16* __restrict__ H,
    h16* __restrict__ Qd, h16* __restrict__ Kd, h16* __restrict__ Vd,
    int K, int ldA, int ldB, int ldC, float scale,
    size_t aBatch, size_t bBatch, size_t cBatch)
{
    extern __shared__ char smem[];
    constexpr uint32_t STG = A_TILE_B + (BTRANS ? BT_TILE_B : B_TILE_B);
    const int nBase = blockIdx.x * 128;
    const int mBase = blockIdx.y * 128;
    if (CAUSAL && nBase >= mBase + 128) return;   // fully-masked tile

    const uint32_t sb = smem_u32(smem);
    const int tid = threadIdx.x;
    const int wid = tid >> 5;
    const int lane = tid & 31;
    const int wm = wid >> 1;        // 0..1 -> m offset wm*64
    const int wn = wid & 1;         // 0..1 -> n offset wn*64

    const h16* aB = A + (size_t)blockIdx.z * aBatch;
    const h16* bB = B + (size_t)blockIdx.z * bBatch;

    int kEnd = K;
    if (TRUNC) { int ke = mBase + 128; kEnd = ke < K ? ke : K; }
    const int nch = kEnd >> 5;      // BK = 32 (always >= 4 here)

    const uint32_t aOff = (uint32_t)((lane & 15) * ROW_B + (lane >> 4) * 16);
    const uint32_t aWarp = (uint32_t)(wm * 64 * ROW_B) + aOff;
    // K-major B (non-trans): row = n, 16B chunk along k
    const uint32_t bOffN = (uint32_t)(((lane & 7) + 8 * (lane >> 4)) * ROW_B + ((lane >> 3) & 1) * 16);
    const uint32_t bWarpN = A_TILE_B + (uint32_t)(wn * 64 * ROW_B) + bOffN;
    // row-major B (trans): row = k, 16B chunk along n
    const uint32_t bOffT = (uint32_t)(((lane & 7) + 8 * ((lane >> 3) & 1)) * BTROW_B + (lane >> 4) * 16);
    const uint32_t bWarpT = A_TILE_B + (uint32_t)(wn * 64 * 2) + bOffT;

    float acc[4][8][4];
    #pragma unroll
    for (int i = 0; i < 4; i++)
        #pragma unroll
        for (int j = 0; j < 8; j++)
            #pragma unroll
            for (int k = 0; k < 4; k++) acc[i][j][k] = 0.0f;

    // prologue: chunks 0..2 into stages 0..2
    #pragma unroll
    for (int s = 0; s < 3; s++) {
        load_stage<BTRANS>(sb + (uint32_t)s * STG, aB, bB, mBase, nBase, ldA, ldB, s * 32, tid);
        asm volatile("cp.async.commit_group;" ::: "memory");
    }

    for (int c = 0; c < nch; c++) {
        asm volatile("cp.async.wait_group 2;" ::: "memory");
        __syncthreads();

        if (c + 3 < nch) {
            int sNext = (c + 3) & 3;
            load_stage<BTRANS>(sb + (uint32_t)sNext * STG, aB, bB, mBase, nBase, ldA, ldB,
                               (c + 3) * 32, tid);
        }
        asm volatile("cp.async.commit_group;" ::: "memory");   // uniform group count

        const uint32_t st = sb + (uint32_t)(c & 3) * STG;
        const uint32_t aAddr = st + aWarp;

        #pragma unroll
        for (int ks = 0; ks < 2; ks++) {
            uint32_t af[4][4];
            #pragma unroll
            for (int mf = 0; mf < 4; mf++)
                ldsm_x4(af[mf], aAddr + (uint32_t)(mf * 16 * ROW_B + ks * 32));
            uint32_t bf[8][2];
            if (BTRANS) {
                const uint32_t bAddr = st + bWarpT + (uint32_t)(ks * 16 * BTROW_B);
                #pragma unroll
                for (int np = 0; np < 4; np++) {
                    uint32_t r4[4];
                    ldsm_x4_t(r4, bAddr + (uint32_t)(np * 32));
                    bf[2 * np][0] = r4[0]; bf[2 * np][1] = r4[1];
                    bf[2 * np + 1][0] = r4[2]; bf[2 * np + 1][1] = r4[3];
                }
            } else {
                const uint32_t bAddr = st + bWarpN + (uint32_t)(ks * 32);
                #pragma unroll
                for (int np = 0; np < 4; np++) {
                    uint32_t r4[4];
                    ldsm_x4(r4, bAddr + (uint32_t)(np * 16 * ROW_B));
                    bf[2 * np][0] = r4[0]; bf[2 * np][1] = r4[1];
                    bf[2 * np + 1][0] = r4[2]; bf[2 * np + 1][1] = r4[3];
                }
            }
            #pragma unroll
            for (int mf = 0; mf < 4; mf++)
                #pragma unroll
                for (int nf = 0; nf < 8; nf++)
                    mma16816h(acc[mf][nf], af[mf], bf[nf]);
        }
    }

    // epilogue
    const int gid = lane >> 2;      // 0..7
    const int tig = lane & 3;       // 0..3

    if (MODE == 2) {
        // QKV: column region selects destination (tile never straddles 1024)
        const int wcol = nBase + wn * 64;
        const int reg = wcol >> 10;                    // 0=Q 1=K 2=V
        h16* dst = (reg == 0) ? Qd : (reg == 1) ? Kd : Vd;
        #pragma unroll
        for (int mf = 0; mf < 4; mf++) {
            const int row0 = mBase + wm * 64 + mf * 16 + gid;
            #pragma unroll
            for (int nf = 0; nf < 8; nf++) {
                const int col0 = nBase + wn * 64 + nf * 8 + 2 * tig;
                float b0 = bias[col0];
                float b1 = bias[col0 + 1];
                const int nloc = col0 - (reg << 10);
                #pragma unroll
                for (int hh = 0; hh < 2; hh++) {
                    const int m = row0 + 8 * hh;
                    float v0 = acc[mf][nf][2 * hh + 0] + b0;
                    float v1 = acc[mf][nf][2 * hh + 1] + b1;
                    *(__half2*)&dst[(size_t)m * DD + nloc] = __floats2half2_rn(v0, v1);
                }
            }
        }
    } else {
        float* Cp = (MODE == 0) ? (C + (size_t)blockIdx.z * cBatch) : nullptr;
        h16*   Hp = (MODE == 1) ? (H + (size_t)blockIdx.z * cBatch) : nullptr;
        #pragma unroll
        for (int mf = 0; mf < 4; mf++) {
            const int row0 = mBase + wm * 64 + mf * 16 + gid;
            #pragma unroll
            for (int nf = 0; nf < 8; nf++) {
                const int col0 = nBase + wn * 64 + nf * 8 + 2 * tig;
                float b0 = BIAS ? bias[col0] : 0.0f;
                float b1 = BIAS ? bias[col0 + 1] : 0.0f;
                #pragma unroll
                for (int hh = 0; hh < 2; hh++) {
                    const int m = row0 + 8 * hh;
                    float v0 = acc[mf][nf][2 * hh + 0] * scale + b0;
                    float v1 = acc[mf][nf][2 * hh + 1] * scale + b1;
                    if (MODE == 0)
                        *(float2*)&Cp[(size_t)m * ldC + col0] = make_float2(v0, v1);
                    else
                        *(__half2*)&Hp[(size_t)m * ldC + col0] = __floats2half2_rn(v0, v1);
                }
            }
        }
    }
}

// ---------------------------------------------------------------------------
// Prep kernels
// ---------------------------------------------------------------------------
__global__ void __launch_bounds__(256) convert_h(const float* __restrict__ in,
                                                 h16* __restrict__ o, size_t n4)
{
    const float4* in4 = (const float4*)in;
    __half2* o2 = (__half2*)o;
    size_t i = (size_t)blockIdx.x * 256 + threadIdx.x;
    size_t stride = (size_t)gridDim.x * 256;
    for (; i < n4; i += stride) {
        float4 v = in4[i];
        o2[2 * i]     = __floats2half2_rn(v.x, v.y);
        o2[2 * i + 1] = __floats2half2_rn(v.z, v.w);
    }
}

__global__ void __launch_bounds__(256) bias_pack(const float* __restrict__ bq,
                                                 const float* __restrict__ bk,
                                                 const float* __restrict__ bv,
                                                 float* __restrict__ o)
{
    int i = blockIdx.x * 256 + threadIdx.x;
    if (i < DD) o[i] = bq[i];
    else if (i < 2 * DD) o[i] = bk[i - DD];
    else if (i < 3 * DD) o[i] = bv[i - 2 * DD];
}

// Fused: out_z[c][r] = (h16)in_z[r][c] for the 4 weight matrices (z selects)
__global__ void __launch_bounds__(256) transpose_wf4(
    const float* __restrict__ w0, const float* __restrict__ w1,
    const float* __restrict__ w2, const float* __restrict__ w3,
    h16* __restrict__ o0, h16* __restrict__ o1,
    h16* __restrict__ o2, h16* __restrict__ o3)
{
    __shared__ float t[32][33];
    const int z = blockIdx.z;
    const float* in = (z == 0) ? w0 : (z == 1) ? w1 : (z == 2) ? w2 : w3;
    h16* o = (z == 0) ? o0 : (z == 1) ? o1 : (z == 2) ? o2 : o3;
    const int x = blockIdx.x * 32;
    const int y = blockIdx.y * 32;
    const int tx = threadIdx.x & 31;
    const int ty = threadIdx.x >> 5;   // 0..7
    #pragma unroll
    for (int i = 0; i < 32; i += 8)
        t[ty + i][tx] = in[(size_t)(y + ty + i) * DD + (x + tx)];
    __syncthreads();
    #pragma unroll
    for (int i = 0; i < 32; i += 8)
        o[(size_t)(x + ty + i) * DD + (y + tx)] = __float2half(t[tx][ty + i]);
}

// ---------------------------------------------------------------------------
// Causal softmax: S fp32 row -> P fp16, zero-padded to next 128-boundary.
// ---------------------------------------------------------------------------
__global__ void __launch_bounds__(256) softmax_causal(const float* __restrict__ S,
                                                      h16* __restrict__ P)
{
    const int r = blockIdx.x;
    const int b = r >> 11;
    const int t = r & (TT - 1);
    const size_t rowOff = (size_t)b * TT * TT + (size_t)t * TT;
    const float* p = S + rowOff;
    h16* ph = P + rowOff;
    const int n = t + 1;

    __shared__ float buf[TT];
    __shared__ float wred[8];
    const int tid = threadIdx.x;
    const int lane = tid & 31;
    const int wrp = tid >> 5;

    float m = -1e30f;
    const int nv = n >> 2;
    const float4* p4 = (const float4*)p;
    float4* b4 = (float4*)buf;
    for (int i = tid; i < nv; i += 256) {
        float4 v = p4[i];
        b4[i] = v;
        m = fmaxf(m, fmaxf(fmaxf(v.x, v.y), fmaxf(v.z, v.w)));
    }
    for (int i = nv * 4 + tid; i < n; i += 256) {
        float v = p[i]; buf[i] = v; m = fmaxf(m, v);
    }
    #pragma unroll
    for (int o = 16; o > 0; o >>= 1) m = fmaxf(m, __shfl_xor_sync(0xFFFFFFFFu, m, o));
    if (lane == 0) wred[wrp] = m;
    __syncthreads();
    float mAll = wred[0];
    #pragma unroll
    for (int w = 1; w < 8; w++) mAll = fmaxf(mAll, wred[w]);
    __syncthreads();

    float sum = 0.0f;
    for (int i = tid; i < nv; i += 256) {
        float4 v = b4[i];
        v.x = __expf(v.x - mAll); v.y = __expf(v.y - mAll);
        v.z = __expf(v.z - mAll); v.w = __expf(v.w - mAll);
        b4[i] = v;
        sum += v.x + v.y + v.z + v.w;
    }
    for (int i = nv * 4 + tid; i < n; i += 256) {
        float e = __expf(buf[i] - mAll); buf[i] = e; sum += e;
    }
    #pragma unroll
    for (int o = 16; o > 0; o >>= 1) sum += __shfl_xor_sync(0xFFFFFFFFu, sum, o);
    if (lane == 0) wred[wrp] = sum;
    __syncthreads();
    float sAll = wred[0];
    #pragma unroll
    for (int w = 1; w < 8; w++) sAll += wred[w];
    const float inv = 1.0f / sAll;

    const int n2 = n >> 1;
    __half2* ph2 = (__half2*)ph;
    for (int i = tid; i < n2; i += 256)
        ph2[i] = __floats2half2_rn(buf[2 * i] * inv, buf[2 * i + 1] * inv);
    if ((n & 1) && tid == 0)
        ph[n - 1] = __float2half(buf[n - 1] * inv);
    const int nPad = ((t >> 7) + 1) << 7;
    const h16 z = __float2half(0.0f);
    for (int i = n + tid; i < nPad; i += 256) ph[i] = z;
}

// ---------------------------------------------------------------------------
// Launch
// ---------------------------------------------------------------------------
extern "C" void kernel_launch(void* const* d_in, const int* in_sizes, int n_in,
                              void* d_out, int out_size)
{
    const float* x  = (const float*)d_in[0];
    const float* Wq = (const float*)d_in[1];
    const float* bq = (const float*)d_in[2];
    const float* Wk = (const float*)d_in[3];
    const float* bk = (const float*)d_in[4];
    const float* Wv = (const float*)d_in[5];
    const float* bv = (const float*)d_in[6];
    const float* Wh = (const float*)d_in[7];
    const float* bh = (const float*)d_in[8];
    float* out = (float*)d_out;

    h16 *x16, *Wqkv, *Wht, *Qp, *Kp, *Vp, *Pp, *Op;
    float *bqkv, *Sp;
    cudaGetSymbolAddress((void**)&x16, g_x16);
    cudaGetSymbolAddress((void**)&Wqkv, g_Wqkv);
    cudaGetSymbolAddress((void**)&bqkv, g_bqkv);
    cudaGetSymbolAddress((void**)&Wht, g_Wht);
    cudaGetSymbolAddress((void**)&Qp, g_Q);
    cudaGetSymbolAddress((void**)&Kp, g_K);
    cudaGetSymbolAddress((void**)&Vp, g_V);
    cudaGetSymbolAddress((void**)&Sp, g_S);
    cudaGetSymbolAddress((void**)&Pp, g_P);
    cudaGetSymbolAddress((void**)&Op, g_O);

    cudaFuncSetAttribute(gemm_tc<2, true,  false, false, false>, cudaFuncAttributeMaxDynamicSharedMemorySize, GEMM_SMEM_N);
    cudaFuncSetAttribute(gemm_tc<0, false, true,  false, false>, cudaFuncAttributeMaxDynamicSharedMemorySize, GEMM_SMEM_N);
    cudaFuncSetAttribute(gemm_tc<1, false, false, true,  true >, cudaFuncAttributeMaxDynamicSharedMemorySize, GEMM_SMEM_T);
    cudaFuncSetAttribute(gemm_tc<0, true,  false, false, false>, cudaFuncAttributeMaxDynamicSharedMemorySize, GEMM_SMEM_N);

    const float scale = 1.0f / 32.0f;   // 1/sqrt(1024)

    // --- prep ---
    convert_h<<<512, 256>>>(x, x16, (size_t)NROWS * DD / 4);
    bias_pack<<<12, 256>>>(bq, bk, bv, bqkv);
    dim3 gW(DD / 32, DD / 32, 4);
    transpose_wf4<<<gW, 256>>>(Wq, Wk, Wv, Wh,
                               Wqkv, Wqkv + (size_t)DD * DD, Wqkv + (size_t)2 * DD * DD, Wht);

    // --- fused QKV projection: [8192,1024] @ [1024,3072] + bias ---
    dim3 gQKV(3 * DD / 128, NROWS / 128, 1);
    gemm_tc<2, true, false, false, false><<<gQKV, NTHR, GEMM_SMEM_N>>>(
        x16, Wqkv, bqkv, nullptr, nullptr, Qp, Kp, Vp,
        DD, DD, DD, 0, 1.0f, 0, 0, 0);

    // --- scores = (Q K^T)/32, causal-skipped tiles ---
    dim3 gScore(TT / 128, TT / 128, BB);
    gemm_tc<0, false, true, false, false><<<gScore, NTHR, GEMM_SMEM_N>>>(
        Qp, Kp, nullptr, Sp, nullptr, nullptr, nullptr, nullptr,
        DD, DD, DD, TT, scale,
        (size_t)TT * DD, (size_t)TT * DD, (size_t)TT * TT);

    // --- softmax -> P fp16 (zero-padded to 128 boundary) ---
    softmax_causal<<<NROWS, 256>>>(Sp, Pp);

    // --- O = P V (K truncated per row tile), V consumed row-major via trans ---
    dim3 gPV(DD / 128, TT / 128, BB);
    gemm_tc<1, false, false, true, true><<<gPV, NTHR, GEMM_SMEM_T>>>(
        Pp, Vp, nullptr, nullptr, Op, nullptr, nullptr, nullptr,
        TT, TT, DD, DD, 1.0f,
        (size_t)TT * TT, (size_t)TT * DD, (size_t)TT * DD);

    // --- out = O Wh + bh ---
    dim3 gOut(DD / 128, NROWS / 128, 1);
    gemm_tc<0, true, false, false, false><<<gOut, NTHR, GEMM_SMEM_N>>>(
        Op, Wht, bh, out, nullptr, nullptr, nullptr, nullptr,
        DD, DD, DD, DD, 1.0f, 0, 0, 0);
}